// round 5
// baseline (speedup 1.0000x reference)
#include <cuda_runtime.h>
#include <cuda_bf16.h>
#include <cstdint>

#define B_  2
#define L_  2048
#define D_  1024
#define S_  256
#define V_  32000
#define M_  (B_*L_)     /* 4096 */
#define S2_ (2*S_)      /* 512  */
#define EPS_ 1e-6f

#define CH_ 32
#define CL_ (L_/CH_)

// ---------------- scratch (__device__ globals; no allocs) ----------------
__device__ __align__(16) float g_ub [M_*S2_];    // packed [ubr | ubi]
__device__ __align__(16) float g_xc [M_*S2_];    // packed [xsr | xsi]
__device__ float g_endr[B_*CH_*S_];
__device__ float g_endi[B_*CH_*S_];
__device__ float g_incr[B_*CH_*S_];
__device__ float g_inci[B_*CH_*S_];
__device__ __align__(1024) __nv_bfloat16 g_uhi[M_*D_];
__device__ __align__(1024) __nv_bfloat16 g_ulo[M_*D_];
__device__ __align__(1024) __nv_bfloat16 g_bchi[D_*S2_];
__device__ __align__(1024) __nv_bfloat16 g_bclo[D_*S2_];
__device__ __align__(1024) __nv_bfloat16 g_xchi[M_*S2_];
__device__ __align__(1024) __nv_bfloat16 g_xclo[M_*S2_];
__device__ __align__(1024) __nv_bfloat16 g_cchi[S2_*D_];
__device__ __align__(1024) __nv_bfloat16 g_cclo[S2_*D_];
__device__ __align__(1024) __nv_bfloat16 g_whi[(size_t)D_*V_];
__device__ __align__(1024) __nv_bfloat16 g_wlo[(size_t)D_*V_];
__device__ __align__(1024) __nv_bfloat16 g_Ghi[(size_t)S2_*V_];
__device__ __align__(1024) __nv_bfloat16 g_Glo[(size_t)S2_*V_];
__device__ float g_gb[V_];

// ---------------- PTX helpers ------------------
__device__ __forceinline__ uint32_t smem_to_u32(const void* p) {
    uint32_t a;
    asm("{ .reg .u64 t; cvta.to.shared.u64 t, %1; cvt.u32.u64 %0, t; }"
        : "=r"(a) : "l"(p));
    return a;
}
__device__ __forceinline__ void cp_async16(uint32_t dst, const void* src) {
    asm volatile("cp.async.cg.shared.global [%0], [%1], 16;"
                 :: "r"(dst), "l"(src) : "memory");
}
#define CP_COMMIT() asm volatile("cp.async.commit_group;" ::: "memory")
#define CP_WAIT(n)  asm volatile("cp.async.wait_group %0;" :: "n"(n) : "memory")

#define LDSM4(r0,r1,r2,r3,a) \
    asm volatile("ldmatrix.sync.aligned.m8n8.x4.shared.b16 {%0,%1,%2,%3}, [%4];" \
        : "=r"(r0), "=r"(r1), "=r"(r2), "=r"(r3) : "r"(a))
#define LDSM4T(r0,r1,r2,r3,a) \
    asm volatile("ldmatrix.sync.aligned.m8n8.x4.trans.shared.b16 {%0,%1,%2,%3}, [%4];" \
        : "=r"(r0), "=r"(r1), "=r"(r2), "=r"(r3) : "r"(a))

#define MMA_BF16(d, a0,a1,a2,a3, b0,b1) \
    asm volatile("mma.sync.aligned.m16n8k16.row.col.f32.bf16.bf16.f32 " \
        "{%0,%1,%2,%3}, {%4,%5,%6,%7}, {%8,%9}, {%0,%1,%2,%3};" \
        : "+f"((d)[0]), "+f"((d)[1]), "+f"((d)[2]), "+f"((d)[3]) \
        : "r"(a0), "r"(a1), "r"(a2), "r"(a3), "r"(b0), "r"(b1))

__inline__ __device__ float warpSum(float v) {
#pragma unroll
    for (int o = 16; o > 0; o >>= 1) v += __shfl_down_sync(0xffffffffu, v, o);
    return v;
}

// =========================================================================
// embedding + double RMSNorm -> bf16 hi/lo
// =========================================================================
__global__ void embed_norm_kernel(const int* __restrict__ ids,
                                  const float* __restrict__ emb,
                                  const float* __restrict__ w1,
                                  const float* __restrict__ w2,
                                  __nv_bfloat16* __restrict__ uhi,
                                  __nv_bfloat16* __restrict__ ulo) {
    int token = blockIdx.x;
    int t = threadIdx.x;
    int id = ids[token];
    const float* e = emb + (size_t)id * D_;

    float v[4]; float ss = 0.f;
#pragma unroll
    for (int i = 0; i < 4; i++) { v[i] = e[t + 256 * i]; ss += v[i] * v[i]; }

    __shared__ float red[8];
    int lane = t & 31, wid = t >> 5;
    float w = warpSum(ss);
    if (lane == 0) red[wid] = w;
    __syncthreads();
    if (wid == 0) {
        float q = (lane < 8) ? red[lane] : 0.f;
        q = warpSum(q);
        if (lane == 0) red[0] = rsqrtf(q / (float)D_ + EPS_);
    }
    __syncthreads();
    float r1 = red[0];
    __syncthreads();

    float x[4]; float ss2 = 0.f;
#pragma unroll
    for (int i = 0; i < 4; i++) {
        x[i] = v[i] * r1 * w1[t + 256 * i];
        ss2 += x[i] * x[i];
    }
    float w2s = warpSum(ss2);
    if (lane == 0) red[wid] = w2s;
    __syncthreads();
    if (wid == 0) {
        float q = (lane < 8) ? red[lane] : 0.f;
        q = warpSum(q);
        if (lane == 0) red[0] = rsqrtf(q / (float)D_ + EPS_);
    }
    __syncthreads();
    float r2 = red[0];
#pragma unroll
    for (int i = 0; i < 4; i++) {
        float val = x[i] * r2 * w2[t + 256 * i];
        size_t o = (size_t)token * D_ + t + 256 * i;
        __nv_bfloat16 h = __float2bfloat16(val);
        uhi[o] = h;
        ulo[o] = __float2bfloat16(val - __bfloat162float(h));
    }
}

// =========================================================================
// Chunked parallel complex scan
// =========================================================================
__global__ void scan_local_kernel(const float* __restrict__ Are,
                                  const float* __restrict__ Aim,
                                  const float* __restrict__ ub,
                                  float* __restrict__ xc,
                                  float* __restrict__ endr,
                                  float* __restrict__ endi) {
    int t = blockIdx.x * blockDim.x + threadIdx.x;
    int s = t % S_;
    int c = (t / S_) % CH_;
    int b = t / (S_ * CH_);
    float ar = Are[s], ai = Aim[s];
    float xr = 0.f, xi = 0.f;
    int tok0 = b * L_ + c * CL_;
    size_t base = (size_t)tok0 * S2_ + s;
    for (int j = 0; j < CL_; j++) {
        size_t o = base + (size_t)j * S2_;
        float ur = ub[o], ui = ub[o + S_];
        float nr = fmaf(ar, xr, fmaf(-ai, xi, ur));
        float ni = fmaf(ar, xi, fmaf(ai, xr, ui));
        xr = nr; xi = ni;
        xc[o] = xr; xc[o + S_] = xi;
    }
    endr[(b * CH_ + c) * S_ + s] = xr;
    endi[(b * CH_ + c) * S_ + s] = xi;
}

__global__ void scan_combine_kernel(const float* __restrict__ Are,
                                    const float* __restrict__ Aim,
                                    const float* __restrict__ endr,
                                    const float* __restrict__ endi,
                                    float* __restrict__ incr,
                                    float* __restrict__ inci) {
    int t = blockIdx.x * blockDim.x + threadIdx.x;
    if (t >= B_ * S_) return;
    int s = t % S_;
    int b = t / S_;
    float ar = Are[s], ai = Aim[s];
    float pr = 1.f, pi = 0.f;
    for (int j = 0; j < CL_; j++) {
        float nr = pr * ar - pi * ai;
        float ni = pr * ai + pi * ar;
        pr = nr; pi = ni;
    }
    float cr = 0.f, ci = 0.f;
    for (int c = 0; c < CH_; c++) {
        int idx = (b * CH_ + c) * S_ + s;
        incr[idx] = cr; inci[idx] = ci;
        float er = endr[idx], ei = endi[idx];
        float nr = fmaf(pr, cr, fmaf(-pi, ci, er));
        float ni = fmaf(pr, ci, fmaf(pi, cr, ei));
        cr = nr; ci = ni;
    }
}

__global__ void scan_fix_kernel(const float* __restrict__ Are,
                                const float* __restrict__ Aim,
                                const float* __restrict__ incr,
                                const float* __restrict__ inci,
                                const float* __restrict__ xc,
                                __nv_bfloat16* __restrict__ xchi,
                                __nv_bfloat16* __restrict__ xclo) {
    int t = blockIdx.x * blockDim.x + threadIdx.x;
    int s = t % S_;
    int c = (t / S_) % CH_;
    int b = t / (S_ * CH_);
    int cidx = (b * CH_ + c) * S_ + s;
    float x0r = incr[cidx], x0i = inci[cidx];
    float ar = Are[s], ai = Aim[s];
    float pr = ar, pi = ai;
    int tok0 = b * L_ + c * CL_;
    size_t base = (size_t)tok0 * S2_ + s;
    for (int j = 0; j < CL_; j++) {
        size_t o = base + (size_t)j * S2_;
        float vr = xc[o]      + (pr * x0r - pi * x0i);
        float vi = xc[o + S_] + (pr * x0i + pi * x0r);
        __nv_bfloat16 hr = __float2bfloat16(vr);
        xchi[o] = hr;
        xclo[o] = __float2bfloat16(vr - __bfloat162float(hr));
        __nv_bfloat16 hi2 = __float2bfloat16(vi);
        xchi[o + S_] = hi2;
        xclo[o + S_] = __float2bfloat16(vi - __bfloat162float(hi2));
        float nr = pr * ar - pi * ai;
        float ni = pr * ai + pi * ar;
        pr = nr; pi = ni;
    }
}

// =========================================================================
// converters
// =========================================================================
__global__ void ccat_kernel(const float* __restrict__ Cre,
                            const float* __restrict__ Cim,
                            __nv_bfloat16* __restrict__ hi,
                            __nv_bfloat16* __restrict__ lo) {
    int i = blockIdx.x * blockDim.x + threadIdx.x;
    int row = i >> 10;
    int d = i & 1023;
    float v = (row < S_) ? Cre[row * D_ + d] : -Cim[(row - S_) * D_ + d];
    __nv_bfloat16 h = __float2bfloat16(v);
    hi[i] = h;
    lo[i] = __float2bfloat16(v - __bfloat162float(h));
}

__global__ void bcat_kernel(const float* __restrict__ Bre,
                            const float* __restrict__ Bim,
                            __nv_bfloat16* __restrict__ hi,
                            __nv_bfloat16* __restrict__ lo) {
    int i = blockIdx.x * blockDim.x + threadIdx.x;   // D_*S2_
    int d = i >> 9;
    int c = i & 511;
    float v = (c < S_) ? Bre[d * S_ + c] : Bim[d * S_ + (c - S_)];
    __nv_bfloat16 h = __float2bfloat16(v);
    hi[i] = h;
    lo[i] = __float2bfloat16(v - __bfloat162float(h));
}

// vectorized: 4 vocab columns per thread, float4 loads, bf16x2 stores
__global__ void wsplit_bias_kernel(const float* __restrict__ Hw,
                                   const float* __restrict__ Dp,
                                   const float* __restrict__ Hb,
                                   __nv_bfloat16* __restrict__ whi,
                                   __nv_bfloat16* __restrict__ wlo,
                                   float* __restrict__ gb) {
    int v4 = (blockIdx.x * blockDim.x + threadIdx.x) * 4;
    if (v4 >= V_) return;
    float a0 = 0.f, a1 = 0.f, a2 = 0.f, a3 = 0.f;
    for (int d = 0; d < D_; d++) {
        size_t o = (size_t)d * V_ + v4;
        float4 w = *(const float4*)(Hw + o);
        __nv_bfloat162 h01, h23, l01, l23;
        h01.x = __float2bfloat16(w.x); h01.y = __float2bfloat16(w.y);
        h23.x = __float2bfloat16(w.z); h23.y = __float2bfloat16(w.w);
        l01.x = __float2bfloat16(w.x - __bfloat162float(h01.x));
        l01.y = __float2bfloat16(w.y - __bfloat162float(h01.y));
        l23.x = __float2bfloat16(w.z - __bfloat162float(h23.x));
        l23.y = __float2bfloat16(w.w - __bfloat162float(h23.y));
        *(__nv_bfloat162*)(whi + o)     = h01;
        *(__nv_bfloat162*)(whi + o + 2) = h23;
        *(__nv_bfloat162*)(wlo + o)     = l01;
        *(__nv_bfloat162*)(wlo + o + 2) = l23;
        float dp = __ldg(Dp + d);
        a0 = fmaf(dp, w.x, a0); a1 = fmaf(dp, w.y, a1);
        a2 = fmaf(dp, w.z, a2); a3 = fmaf(dp, w.w, a3);
    }
    gb[v4]     = a0 + Hb[v4];
    gb[v4 + 1] = a1 + Hb[v4 + 1];
    gb[v4 + 2] = a2 + Hb[v4 + 2];
    gb[v4 + 3] = a3 + Hb[v4 + 3];
}

// =========================================================================
// Split-bf16 HMMA GEMM. CTA tile 128x256, BK=32, 8 warps (2m x 4n, 64x64),
// 3-stage cp.async pipeline. Term-major MMA issue order: each accumulator's
// three split-term MMAs are 32 instructions apart (no RAW back-pressure),
// and lo-fragment LDSMs overlap the hi*hi MMA stream.
// =========================================================================
#define GBM 128
#define GBN 256
#define GBK 32
#define A_STRIDE 80                     /* (32+8)*2B per A row */
#define B_STRIDE 528                    /* (256+8)*2B per B row */
#define A_SPLIT  (128*A_STRIDE)         /* 10240 */
#define A_TOT    (2*A_SPLIT)            /* 20480 */
#define B_SPLIT  (GBK*B_STRIDE)         /* 16896 */
#define STAGE_BYTES (A_TOT + 2*B_SPLIT) /* 54272 */
#define GSMEM (3*STAGE_BYTES)           /* 162816 */

__global__ __launch_bounds__(256, 1)
void mma_gemm(const __nv_bfloat16* __restrict__ Ahi,
              const __nv_bfloat16* __restrict__ Alo,
              const __nv_bfloat16* __restrict__ Bhi,
              const __nv_bfloat16* __restrict__ Blo,
              float* __restrict__ Cf,
              __nv_bfloat16* __restrict__ Chi,
              __nv_bfloat16* __restrict__ Clo,
              const float* __restrict__ bias,
              int Mdim, int Ndim, int Kdim) {
    extern __shared__ char smem[];
    uint32_t sbase = smem_to_u32(smem);
    const int tid = threadIdx.x;
    const int lane = tid & 31, wid = tid >> 5;
    const int wm = wid & 1, wn = wid >> 1;          // 2 x 4 warps
    const int brow = blockIdx.x * GBM;
    const int bcol = blockIdx.y * GBN;
    const int lda = Kdim, ldb = Ndim;
    const int niter = Kdim / GBK;

    float acc[4][8][4];
#pragma unroll
    for (int i = 0; i < 4; i++)
#pragma unroll
        for (int j = 0; j < 8; j++)
#pragma unroll
            for (int k = 0; k < 4; k++) acc[i][j][k] = 0.f;

    auto load_stage = [&](int kt, int st) {
        const int k0 = kt * GBK;
        uint32_t sa = sbase + st * STAGE_BYTES;
#pragma unroll
        for (int i = 0; i < 2; i++) {                // A: 512 16B chunks/split
            int c = tid + i * 256;
            int r = c >> 2, ch = c & 3;
            uint32_t dst = sa + r * A_STRIDE + ch * 16;
            size_t src = (size_t)(brow + r) * lda + k0 + ch * 8;
            cp_async16(dst,           Ahi + src);
            cp_async16(dst + A_SPLIT, Alo + src);
        }
#pragma unroll
        for (int i = 0; i < 4; i++) {                // B: 1024 16B chunks/split
            int c = tid + i * 256;
            int r = c >> 5, ch = c & 31;
            uint32_t dst = sa + A_TOT + r * B_STRIDE + ch * 16;
            size_t src = (size_t)(k0 + r) * ldb + bcol + ch * 8;
            cp_async16(dst,           Bhi + src);
            cp_async16(dst + B_SPLIT, Blo + src);
        }
    };

    load_stage(0, 0); CP_COMMIT();
    load_stage(1, 1); CP_COMMIT();

    for (int kt = 0; kt < niter; kt++) {
        if (kt + 2 < niter) {
            load_stage(kt + 2, (kt + 2) % 3);
            CP_COMMIT();
            CP_WAIT(2);
        } else if (kt + 2 == niter) {
            CP_WAIT(1);
        } else {
            CP_WAIT(0);
        }
        __syncthreads();

        uint32_t sa = sbase + (kt % 3) * STAGE_BYTES;
#pragma unroll
        for (int ks = 0; ks < 2; ks++) {
            // ---- hi fragments ----
            uint32_t ah[4][4], bh[8][2];
#pragma unroll
            for (int mf = 0; mf < 4; mf++) {
                uint32_t addr = sa + (wm * 64 + mf * 16 + (lane & 15)) * A_STRIDE
                              + ks * 32 + (lane >> 4) * 16;
                LDSM4(ah[mf][0], ah[mf][1], ah[mf][2], ah[mf][3], addr);
            }
#pragma unroll
            for (int g = 0; g < 4; g++) {
                uint32_t addr = sa + A_TOT + (ks * 16 + (lane & 15)) * B_STRIDE
                              + (wn * 64 + g * 16 + (lane >> 4) * 8) * 2;
                uint32_t r0, r1, r2, r3;
                LDSM4T(r0, r1, r2, r3, addr);
                bh[2 * g][0] = r0; bh[2 * g][1] = r1;
                bh[2 * g + 1][0] = r2; bh[2 * g + 1][1] = r3;
            }
            // ---- term 1: hi*hi (32 independent MMAs) ----
#pragma unroll
            for (int mf = 0; mf < 4; mf++)
#pragma unroll
                for (int nf = 0; nf < 8; nf++)
                    MMA_BF16(acc[mf][nf], ah[mf][0], ah[mf][1], ah[mf][2], ah[mf][3],
                             bh[nf][0], bh[nf][1]);
            // ---- lo fragments (overlap with hi*hi stream) ----
            uint32_t al[4][4], bl[8][2];
#pragma unroll
            for (int mf = 0; mf < 4; mf++) {
                uint32_t addr = sa + (wm * 64 + mf * 16 + (lane & 15)) * A_STRIDE
                              + ks * 32 + (lane >> 4) * 16;
                LDSM4(al[mf][0], al[mf][1], al[mf][2], al[mf][3], addr + A_SPLIT);
            }
#pragma unroll
            for (int g = 0; g < 4; g++) {
                uint32_t addr = sa + A_TOT + (ks * 16 + (lane & 15)) * B_STRIDE
                              + (wn * 64 + g * 16 + (lane >> 4) * 8) * 2;
                uint32_t r0, r1, r2, r3;
                LDSM4T(r0, r1, r2, r3, addr + B_SPLIT);
                bl[2 * g][0] = r0; bl[2 * g][1] = r1;
                bl[2 * g + 1][0] = r2; bl[2 * g + 1][1] = r3;
            }
            // ---- term 2: lo*hi ----
#pragma unroll
            for (int mf = 0; mf < 4; mf++)
#pragma unroll
                for (int nf = 0; nf < 8; nf++)
                    MMA_BF16(acc[mf][nf], al[mf][0], al[mf][1], al[mf][2], al[mf][3],
                             bh[nf][0], bh[nf][1]);
            // ---- term 3: hi*lo ----
#pragma unroll
            for (int mf = 0; mf < 4; mf++)
#pragma unroll
                for (int nf = 0; nf < 8; nf++)
                    MMA_BF16(acc[mf][nf], ah[mf][0], ah[mf][1], ah[mf][2], ah[mf][3],
                             bl[nf][0], bl[nf][1]);
        }
        __syncthreads();
    }

    if (Chi) {
#pragma unroll
        for (int mf = 0; mf < 4; mf++) {
            int r0 = brow + wm * 64 + mf * 16 + (lane >> 2);
#pragma unroll
            for (int nf = 0; nf < 8; nf++) {
                int c0 = bcol + wn * 64 + nf * 8 + (lane & 3) * 2;
#pragma unroll
                for (int half = 0; half < 2; half++) {
                    float v0 = acc[mf][nf][2 * half];
                    float v1 = acc[mf][nf][2 * half + 1];
                    __nv_bfloat16 h0 = __float2bfloat16(v0);
                    __nv_bfloat16 h1 = __float2bfloat16(v1);
                    __nv_bfloat162 hv; hv.x = h0; hv.y = h1;
                    __nv_bfloat162 lv;
                    lv.x = __float2bfloat16(v0 - __bfloat162float(h0));
                    lv.y = __float2bfloat16(v1 - __bfloat162float(h1));
                    size_t off = (size_t)(r0 + 8 * half) * Ndim + c0;
                    *(__nv_bfloat162*)(Chi + off) = hv;
                    *(__nv_bfloat162*)(Clo + off) = lv;
                }
            }
        }
    } else {
#pragma unroll
        for (int mf = 0; mf < 4; mf++) {
            int r0 = brow + wm * 64 + mf * 16 + (lane >> 2);
#pragma unroll
            for (int nf = 0; nf < 8; nf++) {
                int c0 = bcol + wn * 64 + nf * 8 + (lane & 3) * 2;
                float b0 = 0.f, b1 = 0.f;
                if (bias) { b0 = __ldg(bias + c0); b1 = __ldg(bias + c0 + 1); }
                float2 v0 = make_float2(acc[mf][nf][0] + b0, acc[mf][nf][1] + b1);
                float2 v1 = make_float2(acc[mf][nf][2] + b0, acc[mf][nf][3] + b1);
                *(float2*)(Cf + (size_t)r0 * Ndim + c0)       = v0;
                *(float2*)(Cf + (size_t)(r0 + 8) * Ndim + c0) = v1;
            }
        }
    }
}

// =========================================================================
extern "C" void kernel_launch(void* const* d_in, const int* in_sizes, int n_in,
                              void* d_out, int out_size) {
    const int*   ids = (const int*)  d_in[0];
    const float* emb = (const float*)d_in[1];
    const float* w1  = (const float*)d_in[2];
    const float* w2  = (const float*)d_in[3];
    const float* Are = (const float*)d_in[4];
    const float* Aim = (const float*)d_in[5];
    const float* Bre = (const float*)d_in[6];
    const float* Bim = (const float*)d_in[7];
    const float* Cre = (const float*)d_in[8];
    const float* Cim = (const float*)d_in[9];
    const float* Dp  = (const float*)d_in[10];
    const float* Hw  = (const float*)d_in[11];
    const float* Hb  = (const float*)d_in[12];
    float* out = (float*)d_out;

    float *ub, *xc, *endr, *endi, *incr, *inci, *gb;
    __nv_bfloat16 *uhi, *ulo, *bchi, *bclo, *xchi, *xclo;
    __nv_bfloat16 *cchi, *cclo, *whi, *wlo, *Ghi, *Glo;
    cudaGetSymbolAddress((void**)&ub,   g_ub);
    cudaGetSymbolAddress((void**)&xc,   g_xc);
    cudaGetSymbolAddress((void**)&endr, g_endr);
    cudaGetSymbolAddress((void**)&endi, g_endi);
    cudaGetSymbolAddress((void**)&incr, g_incr);
    cudaGetSymbolAddress((void**)&inci, g_inci);
    cudaGetSymbolAddress((void**)&uhi,  g_uhi);
    cudaGetSymbolAddress((void**)&ulo,  g_ulo);
    cudaGetSymbolAddress((void**)&bchi, g_bchi);
    cudaGetSymbolAddress((void**)&bclo, g_bclo);
    cudaGetSymbolAddress((void**)&xchi, g_xchi);
    cudaGetSymbolAddress((void**)&xclo, g_xclo);
    cudaGetSymbolAddress((void**)&cchi, g_cchi);
    cudaGetSymbolAddress((void**)&cclo, g_cclo);
    cudaGetSymbolAddress((void**)&whi,  g_whi);
    cudaGetSymbolAddress((void**)&wlo,  g_wlo);
    cudaGetSymbolAddress((void**)&Ghi,  g_Ghi);
    cudaGetSymbolAddress((void**)&Glo,  g_Glo);
    cudaGetSymbolAddress((void**)&gb,   g_gb);

    cudaFuncSetAttribute(mma_gemm,
                         cudaFuncAttributeMaxDynamicSharedMemorySize, GSMEM);

    // ---- weight prep ----
    wsplit_bias_kernel<<<(V_ / 4 + 255) / 256, 256>>>(Hw, Dp, Hb, whi, wlo, gb);
    ccat_kernel<<<(S2_ * D_) / 256, 256>>>(Cre, Cim, cchi, cclo);
    bcat_kernel<<<(D_ * S2_) / 256, 256>>>(Bre, Bim, bchi, bclo);

    // G = Ccat @ Hw  [512, 32000], bf16 hi/lo epilogue
    mma_gemm<<<dim3(S2_ / GBM, V_ / GBN), 256, GSMEM>>>(
        cchi, cclo, whi, wlo, nullptr, Ghi, Glo, nullptr, S2_, V_, D_);

    // ---- activation chain ----
    embed_norm_kernel<<<M_, 256>>>(ids, emb, w1, w2, uhi, ulo);

    // uB = u @ Bcat  [4096, 512] fp32, packed [re|im]
    mma_gemm<<<dim3(M_ / GBM, S2_ / GBN), 256, GSMEM>>>(
        uhi, ulo, bchi, bclo, ub, nullptr, nullptr, nullptr, M_, S2_, D_);

    // parallel complex scan -> xchi/xclo
    scan_local_kernel<<<(B_ * CH_ * S_) / 256, 256>>>(Are, Aim, ub, xc, endr, endi);
    scan_combine_kernel<<<(B_ * S_ + 255) / 256, 256>>>(Are, Aim, endr, endi, incr, inci);
    scan_fix_kernel<<<(B_ * CH_ * S_) / 256, 256>>>(Are, Aim, incr, inci, xc, xchi, xclo);

    // logits = xc @ G + gb  [4096, 32000]
    mma_gemm<<<dim3(M_ / GBM, V_ / GBN), 256, GSMEM>>>(
        xchi, xclo, Ghi, Glo, out, nullptr, nullptr, gb, M_, V_, S2_);
}

// round 6
// speedup vs baseline: 1.0015x; 1.0015x over previous
#include <cuda_runtime.h>
#include <cuda_bf16.h>
#include <cstdint>

#define B_  2
#define L_  2048
#define D_  1024
#define S_  256
#define V_  32000
#define M_  (B_*L_)     /* 4096 */
#define S2_ (2*S_)      /* 512  */
#define EPS_ 1e-6f

#define CH_ 32
#define CL_ (L_/CH_)

// ---------------- scratch (__device__ globals; no allocs) ----------------
__device__ __align__(16) float g_ub [M_*S2_];    // packed [ubr | ubi]
__device__ __align__(16) float g_xc [M_*S2_];    // packed [xsr | xsi]
__device__ float g_endr[B_*CH_*S_];
__device__ float g_endi[B_*CH_*S_];
__device__ float g_incr[B_*CH_*S_];
__device__ float g_inci[B_*CH_*S_];
__device__ __align__(1024) __nv_bfloat16 g_uhi[M_*D_];
__device__ __align__(1024) __nv_bfloat16 g_ulo[M_*D_];
__device__ __align__(1024) __nv_bfloat16 g_bchi[D_*S2_];
__device__ __align__(1024) __nv_bfloat16 g_bclo[D_*S2_];
__device__ __align__(1024) __nv_bfloat16 g_xchi[M_*S2_];
__device__ __align__(1024) __nv_bfloat16 g_xclo[M_*S2_];
__device__ __align__(1024) __nv_bfloat16 g_cchi[S2_*D_];
__device__ __align__(1024) __nv_bfloat16 g_cclo[S2_*D_];
__device__ __align__(1024) __nv_bfloat16 g_whi[(size_t)D_*V_];
__device__ __align__(1024) __nv_bfloat16 g_wlo[(size_t)D_*V_];
__device__ __align__(1024) __nv_bfloat16 g_Ghi[(size_t)S2_*V_];
__device__ __align__(1024) __nv_bfloat16 g_Glo[(size_t)S2_*V_];
__device__ float g_gb[V_];

// ---------------- PTX helpers ------------------
__device__ __forceinline__ uint32_t smem_to_u32(const void* p) {
    uint32_t a;
    asm("{ .reg .u64 t; cvta.to.shared.u64 t, %1; cvt.u32.u64 %0, t; }"
        : "=r"(a) : "l"(p));
    return a;
}
__device__ __forceinline__ void cp_async16(uint32_t dst, const void* src) {
    asm volatile("cp.async.cg.shared.global [%0], [%1], 16;"
                 :: "r"(dst), "l"(src) : "memory");
}
#define CP_COMMIT() asm volatile("cp.async.commit_group;" ::: "memory")
#define CP_WAIT(n)  asm volatile("cp.async.wait_group %0;" :: "n"(n) : "memory")

#define LDSM4(r0,r1,r2,r3,a) \
    asm volatile("ldmatrix.sync.aligned.m8n8.x4.shared.b16 {%0,%1,%2,%3}, [%4];" \
        : "=r"(r0), "=r"(r1), "=r"(r2), "=r"(r3) : "r"(a))
#define LDSM4T(r0,r1,r2,r3,a) \
    asm volatile("ldmatrix.sync.aligned.m8n8.x4.trans.shared.b16 {%0,%1,%2,%3}, [%4];" \
        : "=r"(r0), "=r"(r1), "=r"(r2), "=r"(r3) : "r"(a))

#define MMA_BF16(d, a0,a1,a2,a3, b0,b1) \
    asm volatile("mma.sync.aligned.m16n8k16.row.col.f32.bf16.bf16.f32 " \
        "{%0,%1,%2,%3}, {%4,%5,%6,%7}, {%8,%9}, {%0,%1,%2,%3};" \
        : "+f"((d)[0]), "+f"((d)[1]), "+f"((d)[2]), "+f"((d)[3]) \
        : "r"(a0), "r"(a1), "r"(a2), "r"(a3), "r"(b0), "r"(b1))

__inline__ __device__ float warpSum(float v) {
#pragma unroll
    for (int o = 16; o > 0; o >>= 1) v += __shfl_down_sync(0xffffffffu, v, o);
    return v;
}

// =========================================================================
// embedding + double RMSNorm -> bf16 hi/lo
// =========================================================================
__global__ void embed_norm_kernel(const int* __restrict__ ids,
                                  const float* __restrict__ emb,
                                  const float* __restrict__ w1,
                                  const float* __restrict__ w2,
                                  __nv_bfloat16* __restrict__ uhi,
                                  __nv_bfloat16* __restrict__ ulo) {
    int token = blockIdx.x;
    int t = threadIdx.x;
    int id = ids[token];
    const float* e = emb + (size_t)id * D_;

    float v[4]; float ss = 0.f;
#pragma unroll
    for (int i = 0; i < 4; i++) { v[i] = e[t + 256 * i]; ss += v[i] * v[i]; }

    __shared__ float red[8];
    int lane = t & 31, wid = t >> 5;
    float w = warpSum(ss);
    if (lane == 0) red[wid] = w;
    __syncthreads();
    if (wid == 0) {
        float q = (lane < 8) ? red[lane] : 0.f;
        q = warpSum(q);
        if (lane == 0) red[0] = rsqrtf(q / (float)D_ + EPS_);
    }
    __syncthreads();
    float r1 = red[0];
    __syncthreads();

    float x[4]; float ss2 = 0.f;
#pragma unroll
    for (int i = 0; i < 4; i++) {
        x[i] = v[i] * r1 * w1[t + 256 * i];
        ss2 += x[i] * x[i];
    }
    float w2s = warpSum(ss2);
    if (lane == 0) red[wid] = w2s;
    __syncthreads();
    if (wid == 0) {
        float q = (lane < 8) ? red[lane] : 0.f;
        q = warpSum(q);
        if (lane == 0) red[0] = rsqrtf(q / (float)D_ + EPS_);
    }
    __syncthreads();
    float r2 = red[0];
#pragma unroll
    for (int i = 0; i < 4; i++) {
        float val = x[i] * r2 * w2[t + 256 * i];
        size_t o = (size_t)token * D_ + t + 256 * i;
        __nv_bfloat16 h = __float2bfloat16(val);
        uhi[o] = h;
        ulo[o] = __float2bfloat16(val - __bfloat162float(h));
    }
}

// =========================================================================
// Chunked parallel complex scan
// =========================================================================
__global__ void scan_local_kernel(const float* __restrict__ Are,
                                  const float* __restrict__ Aim,
                                  const float* __restrict__ ub,
                                  float* __restrict__ xc,
                                  float* __restrict__ endr,
                                  float* __restrict__ endi) {
    int t = blockIdx.x * blockDim.x + threadIdx.x;
    int s = t % S_;
    int c = (t / S_) % CH_;
    int b = t / (S_ * CH_);
    float ar = Are[s], ai = Aim[s];
    float xr = 0.f, xi = 0.f;
    int tok0 = b * L_ + c * CL_;
    size_t base = (size_t)tok0 * S2_ + s;
    for (int j = 0; j < CL_; j++) {
        size_t o = base + (size_t)j * S2_;
        float ur = ub[o], ui = ub[o + S_];
        float nr = fmaf(ar, xr, fmaf(-ai, xi, ur));
        float ni = fmaf(ar, xi, fmaf(ai, xr, ui));
        xr = nr; xi = ni;
        xc[o] = xr; xc[o + S_] = xi;
    }
    endr[(b * CH_ + c) * S_ + s] = xr;
    endi[(b * CH_ + c) * S_ + s] = xi;
}

__global__ void scan_combine_kernel(const float* __restrict__ Are,
                                    const float* __restrict__ Aim,
                                    const float* __restrict__ endr,
                                    const float* __restrict__ endi,
                                    float* __restrict__ incr,
                                    float* __restrict__ inci) {
    int t = blockIdx.x * blockDim.x + threadIdx.x;
    if (t >= B_ * S_) return;
    int s = t % S_;
    int b = t / S_;
    float ar = Are[s], ai = Aim[s];
    float pr = 1.f, pi = 0.f;
    for (int j = 0; j < CL_; j++) {
        float nr = pr * ar - pi * ai;
        float ni = pr * ai + pi * ar;
        pr = nr; pi = ni;
    }
    float cr = 0.f, ci = 0.f;
    for (int c = 0; c < CH_; c++) {
        int idx = (b * CH_ + c) * S_ + s;
        incr[idx] = cr; inci[idx] = ci;
        float er = endr[idx], ei = endi[idx];
        float nr = fmaf(pr, cr, fmaf(-pi, ci, er));
        float ni = fmaf(pr, ci, fmaf(pi, cr, ei));
        cr = nr; ci = ni;
    }
}

__global__ void scan_fix_kernel(const float* __restrict__ Are,
                                const float* __restrict__ Aim,
                                const float* __restrict__ incr,
                                const float* __restrict__ inci,
                                const float* __restrict__ xc,
                                __nv_bfloat16* __restrict__ xchi,
                                __nv_bfloat16* __restrict__ xclo) {
    int t = blockIdx.x * blockDim.x + threadIdx.x;
    int s = t % S_;
    int c = (t / S_) % CH_;
    int b = t / (S_ * CH_);
    int cidx = (b * CH_ + c) * S_ + s;
    float x0r = incr[cidx], x0i = inci[cidx];
    float ar = Are[s], ai = Aim[s];
    float pr = ar, pi = ai;
    int tok0 = b * L_ + c * CL_;
    size_t base = (size_t)tok0 * S2_ + s;
    for (int j = 0; j < CL_; j++) {
        size_t o = base + (size_t)j * S2_;
        float vr = xc[o]      + (pr * x0r - pi * x0i);
        float vi = xc[o + S_] + (pr * x0i + pi * x0r);
        __nv_bfloat16 hr = __float2bfloat16(vr);
        xchi[o] = hr;
        xclo[o] = __float2bfloat16(vr - __bfloat162float(hr));
        __nv_bfloat16 hi2 = __float2bfloat16(vi);
        xchi[o + S_] = hi2;
        xclo[o + S_] = __float2bfloat16(vi - __bfloat162float(hi2));
        float nr = pr * ar - pi * ai;
        float ni = pr * ai + pi * ar;
        pr = nr; pi = ni;
    }
}

// =========================================================================
// converters
// =========================================================================
__global__ void ccat_kernel(const float* __restrict__ Cre,
                            const float* __restrict__ Cim,
                            __nv_bfloat16* __restrict__ hi,
                            __nv_bfloat16* __restrict__ lo) {
    int i = blockIdx.x * blockDim.x + threadIdx.x;
    int row = i >> 10;
    int d = i & 1023;
    float v = (row < S_) ? Cre[row * D_ + d] : -Cim[(row - S_) * D_ + d];
    __nv_bfloat16 h = __float2bfloat16(v);
    hi[i] = h;
    lo[i] = __float2bfloat16(v - __bfloat162float(h));
}

__global__ void bcat_kernel(const float* __restrict__ Bre,
                            const float* __restrict__ Bim,
                            __nv_bfloat16* __restrict__ hi,
                            __nv_bfloat16* __restrict__ lo) {
    int i = blockIdx.x * blockDim.x + threadIdx.x;   // D_*S2_
    int d = i >> 9;
    int c = i & 511;
    float v = (c < S_) ? Bre[d * S_ + c] : Bim[d * S_ + (c - S_)];
    __nv_bfloat16 h = __float2bfloat16(v);
    hi[i] = h;
    lo[i] = __float2bfloat16(v - __bfloat162float(h));
}

// vectorized: 4 vocab columns per thread
__global__ void wsplit_bias_kernel(const float* __restrict__ Hw,
                                   const float* __restrict__ Dp,
                                   const float* __restrict__ Hb,
                                   __nv_bfloat16* __restrict__ whi,
                                   __nv_bfloat16* __restrict__ wlo,
                                   float* __restrict__ gb) {
    int v4 = (blockIdx.x * blockDim.x + threadIdx.x) * 4;
    if (v4 >= V_) return;
    float a0 = 0.f, a1 = 0.f, a2 = 0.f, a3 = 0.f;
    for (int d = 0; d < D_; d++) {
        size_t o = (size_t)d * V_ + v4;
        float4 w = *(const float4*)(Hw + o);
        __nv_bfloat162 h01, h23, l01, l23;
        h01.x = __float2bfloat16(w.x); h01.y = __float2bfloat16(w.y);
        h23.x = __float2bfloat16(w.z); h23.y = __float2bfloat16(w.w);
        l01.x = __float2bfloat16(w.x - __bfloat162float(h01.x));
        l01.y = __float2bfloat16(w.y - __bfloat162float(h01.y));
        l23.x = __float2bfloat16(w.z - __bfloat162float(h23.x));
        l23.y = __float2bfloat16(w.w - __bfloat162float(h23.y));
        *(__nv_bfloat162*)(whi + o)     = h01;
        *(__nv_bfloat162*)(whi + o + 2) = h23;
        *(__nv_bfloat162*)(wlo + o)     = l01;
        *(__nv_bfloat162*)(wlo + o + 2) = l23;
        float dp = __ldg(Dp + d);
        a0 = fmaf(dp, w.x, a0); a1 = fmaf(dp, w.y, a1);
        a2 = fmaf(dp, w.z, a2); a3 = fmaf(dp, w.w, a3);
    }
    gb[v4]     = a0 + Hb[v4];
    gb[v4 + 1] = a1 + Hb[v4 + 1];
    gb[v4 + 2] = a2 + Hb[v4 + 2];
    gb[v4 + 3] = a3 + Hb[v4 + 3];
}

// =========================================================================
// Split-bf16 HMMA GEMM. CTA tile 128x256, BK=32, 16 warps (2m x 8n, 64x32
// warp tile), 3-stage cp.async pipeline, term-staged fragment lifetimes to
// fit 128 regs/thread (acc 64 + peak frags ~40). occ target: 4 warps/SMSP.
// =========================================================================
#define GBM 128
#define GBN 256
#define GBK 32
#define NT  512
#define A_STRIDE 80                     /* (32+8)*2B per A row */
#define B_STRIDE 528                    /* (256+8)*2B per B row */
#define A_SPLIT  (128*A_STRIDE)         /* 10240 */
#define A_TOT    (2*A_SPLIT)            /* 20480 */
#define B_SPLIT  (GBK*B_STRIDE)         /* 16896 */
#define STAGE_BYTES (A_TOT + 2*B_SPLIT) /* 54272 */
#define GSMEM (3*STAGE_BYTES)           /* 162816 */

__global__ __launch_bounds__(NT, 1)
void mma_gemm(const __nv_bfloat16* __restrict__ Ahi,
              const __nv_bfloat16* __restrict__ Alo,
              const __nv_bfloat16* __restrict__ Bhi,
              const __nv_bfloat16* __restrict__ Blo,
              float* __restrict__ Cf,
              __nv_bfloat16* __restrict__ Chi,
              __nv_bfloat16* __restrict__ Clo,
              const float* __restrict__ bias,
              int Mdim, int Ndim, int Kdim) {
    extern __shared__ char smem[];
    uint32_t sbase = smem_to_u32(smem);
    const int tid = threadIdx.x;
    const int lane = tid & 31, wid = tid >> 5;
    const int wm = wid & 1, wn = wid >> 1;          // 2m x 8n warps, 64x32 tile
    const int brow = blockIdx.x * GBM;
    const int bcol = blockIdx.y * GBN;
    const int lda = Kdim, ldb = Ndim;
    const int niter = Kdim / GBK;

    float acc[4][4][4];                              // 64 regs
#pragma unroll
    for (int i = 0; i < 4; i++)
#pragma unroll
        for (int j = 0; j < 4; j++)
#pragma unroll
            for (int k = 0; k < 4; k++) acc[i][j][k] = 0.f;

    auto load_stage = [&](int kt, int st) {
        const int k0 = kt * GBK;
        uint32_t sa = sbase + st * STAGE_BYTES;
        {                                            // A: 512 chunks per split
            int r = tid >> 2, ch = tid & 3;
            uint32_t dst = sa + r * A_STRIDE + ch * 16;
            size_t src = (size_t)(brow + r) * lda + k0 + ch * 8;
            cp_async16(dst,           Ahi + src);
            cp_async16(dst + A_SPLIT, Alo + src);
        }
#pragma unroll
        for (int i = 0; i < 2; i++) {                // B: 1024 chunks per split
            int c = tid + i * NT;
            int r = c >> 5, ch = c & 31;
            uint32_t dst = sa + A_TOT + r * B_STRIDE + ch * 16;
            size_t src = (size_t)(k0 + r) * ldb + bcol + ch * 8;
            cp_async16(dst,           Bhi + src);
            cp_async16(dst + B_SPLIT, Blo + src);
        }
    };

    load_stage(0, 0); CP_COMMIT();
    load_stage(1, 1); CP_COMMIT();

    for (int kt = 0; kt < niter; kt++) {
        if (kt + 2 < niter) {
            load_stage(kt + 2, (kt + 2) % 3);
            CP_COMMIT();
            CP_WAIT(2);
        } else if (kt + 2 == niter) {
            CP_WAIT(1);
        } else {
            CP_WAIT(0);
        }
        __syncthreads();

        uint32_t sa = sbase + (kt % 3) * STAGE_BYTES;
        uint32_t a_base = sa + (wm * 64 + (lane & 15)) * A_STRIDE + (lane >> 4) * 16;
        uint32_t b_base = sa + A_TOT + (lane & 15) * B_STRIDE
                        + (wn * 32 + (lane >> 4) * 8) * 2;
#pragma unroll
        for (int ks = 0; ks < 2; ks++) {
            uint32_t a_ks = a_base + ks * 32;
            uint32_t b_ks = b_base + ks * 16 * B_STRIDE;

            // hi fragments
            uint32_t ah[4][4], bh[4][2];
#pragma unroll
            for (int mf = 0; mf < 4; mf++)
                LDSM4(ah[mf][0], ah[mf][1], ah[mf][2], ah[mf][3],
                      a_ks + mf * 16 * A_STRIDE);
#pragma unroll
            for (int g = 0; g < 2; g++) {
                uint32_t r0, r1, r2, r3;
                LDSM4T(r0, r1, r2, r3, b_ks + g * 32);
                bh[2 * g][0] = r0; bh[2 * g][1] = r1;
                bh[2 * g + 1][0] = r2; bh[2 * g + 1][1] = r3;
            }
            // term 1: hi*hi
#pragma unroll
            for (int mf = 0; mf < 4; mf++)
#pragma unroll
                for (int nf = 0; nf < 4; nf++)
                    MMA_BF16(acc[mf][nf], ah[mf][0], ah[mf][1], ah[mf][2], ah[mf][3],
                             bh[nf][0], bh[nf][1]);
            // lo A fragments; term 2: lo*hi
            {
                uint32_t al[4][4];
#pragma unroll
                for (int mf = 0; mf < 4; mf++)
                    LDSM4(al[mf][0], al[mf][1], al[mf][2], al[mf][3],
                          a_ks + mf * 16 * A_STRIDE + A_SPLIT);
#pragma unroll
                for (int mf = 0; mf < 4; mf++)
#pragma unroll
                    for (int nf = 0; nf < 4; nf++)
                        MMA_BF16(acc[mf][nf], al[mf][0], al[mf][1], al[mf][2], al[mf][3],
                                 bh[nf][0], bh[nf][1]);
            }
            // lo B fragments; term 3: hi*lo
            {
                uint32_t bl[4][2];
#pragma unroll
                for (int g = 0; g < 2; g++) {
                    uint32_t r0, r1, r2, r3;
                    LDSM4T(r0, r1, r2, r3, b_ks + g * 32 + B_SPLIT);
                    bl[2 * g][0] = r0; bl[2 * g][1] = r1;
                    bl[2 * g + 1][0] = r2; bl[2 * g + 1][1] = r3;
                }
#pragma unroll
                for (int mf = 0; mf < 4; mf++)
#pragma unroll
                    for (int nf = 0; nf < 4; nf++)
                        MMA_BF16(acc[mf][nf], ah[mf][0], ah[mf][1], ah[mf][2], ah[mf][3],
                                 bl[nf][0], bl[nf][1]);
            }
        }
        __syncthreads();
    }

    if (Chi) {
#pragma unroll
        for (int mf = 0; mf < 4; mf++) {
            int r0 = brow + wm * 64 + mf * 16 + (lane >> 2);
#pragma unroll
            for (int nf = 0; nf < 4; nf++) {
                int c0 = bcol + wn * 32 + nf * 8 + (lane & 3) * 2;
#pragma unroll
                for (int half = 0; half < 2; half++) {
                    float v0 = acc[mf][nf][2 * half];
                    float v1 = acc[mf][nf][2 * half + 1];
                    __nv_bfloat16 h0 = __float2bfloat16(v0);
                    __nv_bfloat16 h1 = __float2bfloat16(v1);
                    __nv_bfloat162 hv; hv.x = h0; hv.y = h1;
                    __nv_bfloat162 lv;
                    lv.x = __float2bfloat16(v0 - __bfloat162float(h0));
                    lv.y = __float2bfloat16(v1 - __bfloat162float(h1));
                    size_t off = (size_t)(r0 + 8 * half) * Ndim + c0;
                    *(__nv_bfloat162*)(Chi + off) = hv;
                    *(__nv_bfloat162*)(Clo + off) = lv;
                }
            }
        }
    } else {
#pragma unroll
        for (int mf = 0; mf < 4; mf++) {
            int r0 = brow + wm * 64 + mf * 16 + (lane >> 2);
#pragma unroll
            for (int nf = 0; nf < 4; nf++) {
                int c0 = bcol + wn * 32 + nf * 8 + (lane & 3) * 2;
                float b0 = 0.f, b1 = 0.f;
                if (bias) { b0 = __ldg(bias + c0); b1 = __ldg(bias + c0 + 1); }
                float2 v0 = make_float2(acc[mf][nf][0] + b0, acc[mf][nf][1] + b1);
                float2 v1 = make_float2(acc[mf][nf][2] + b0, acc[mf][nf][3] + b1);
                *(float2*)(Cf + (size_t)r0 * Ndim + c0)       = v0;
                *(float2*)(Cf + (size_t)(r0 + 8) * Ndim + c0) = v1;
            }
        }
    }
}

// =========================================================================
extern "C" void kernel_launch(void* const* d_in, const int* in_sizes, int n_in,
                              void* d_out, int out_size) {
    const int*   ids = (const int*)  d_in[0];
    const float* emb = (const float*)d_in[1];
    const float* w1  = (const float*)d_in[2];
    const float* w2  = (const float*)d_in[3];
    const float* Are = (const float*)d_in[4];
    const float* Aim = (const float*)d_in[5];
    const float* Bre = (const float*)d_in[6];
    const float* Bim = (const float*)d_in[7];
    const float* Cre = (const float*)d_in[8];
    const float* Cim = (const float*)d_in[9];
    const float* Dp  = (const float*)d_in[10];
    const float* Hw  = (const float*)d_in[11];
    const float* Hb  = (const float*)d_in[12];
    float* out = (float*)d_out;

    float *ub, *xc, *endr, *endi, *incr, *inci, *gb;
    __nv_bfloat16 *uhi, *ulo, *bchi, *bclo, *xchi, *xclo;
    __nv_bfloat16 *cchi, *cclo, *whi, *wlo, *Ghi, *Glo;
    cudaGetSymbolAddress((void**)&ub,   g_ub);
    cudaGetSymbolAddress((void**)&xc,   g_xc);
    cudaGetSymbolAddress((void**)&endr, g_endr);
    cudaGetSymbolAddress((void**)&endi, g_endi);
    cudaGetSymbolAddress((void**)&incr, g_incr);
    cudaGetSymbolAddress((void**)&inci, g_inci);
    cudaGetSymbolAddress((void**)&uhi,  g_uhi);
    cudaGetSymbolAddress((void**)&ulo,  g_ulo);
    cudaGetSymbolAddress((void**)&bchi, g_bchi);
    cudaGetSymbolAddress((void**)&bclo, g_bclo);
    cudaGetSymbolAddress((void**)&xchi, g_xchi);
    cudaGetSymbolAddress((void**)&xclo, g_xclo);
    cudaGetSymbolAddress((void**)&cchi, g_cchi);
    cudaGetSymbolAddress((void**)&cclo, g_cclo);
    cudaGetSymbolAddress((void**)&whi,  g_whi);
    cudaGetSymbolAddress((void**)&wlo,  g_wlo);
    cudaGetSymbolAddress((void**)&Ghi,  g_Ghi);
    cudaGetSymbolAddress((void**)&Glo,  g_Glo);
    cudaGetSymbolAddress((void**)&gb,   g_gb);

    cudaFuncSetAttribute(mma_gemm,
                         cudaFuncAttributeMaxDynamicSharedMemorySize, GSMEM);

    // ---- weight prep ----
    wsplit_bias_kernel<<<(V_ / 4 + 255) / 256, 256>>>(Hw, Dp, Hb, whi, wlo, gb);
    ccat_kernel<<<(S2_ * D_) / 256, 256>>>(Cre, Cim, cchi, cclo);
    bcat_kernel<<<(D_ * S2_) / 256, 256>>>(Bre, Bim, bchi, bclo);

    // G = Ccat @ Hw  [512, 32000], bf16 hi/lo epilogue
    mma_gemm<<<dim3(S2_ / GBM, V_ / GBN), NT, GSMEM>>>(
        cchi, cclo, whi, wlo, nullptr, Ghi, Glo, nullptr, S2_, V_, D_);

    // ---- activation chain ----
    embed_norm_kernel<<<M_, 256>>>(ids, emb, w1, w2, uhi, ulo);

    // uB = u @ Bcat  [4096, 512] fp32, packed [re|im]
    mma_gemm<<<dim3(M_ / GBM, S2_ / GBN), NT, GSMEM>>>(
        uhi, ulo, bchi, bclo, ub, nullptr, nullptr, nullptr, M_, S2_, D_);

    // parallel complex scan -> xchi/xclo
    scan_local_kernel<<<(B_ * CH_ * S_) / 256, 256>>>(Are, Aim, ub, xc, endr, endi);
    scan_combine_kernel<<<(B_ * S_ + 255) / 256, 256>>>(Are, Aim, endr, endi, incr, inci);
    scan_fix_kernel<<<(B_ * CH_ * S_) / 256, 256>>>(Are, Aim, incr, inci, xc, xchi, xclo);

    // logits = xc @ G + gb  [4096, 32000]
    mma_gemm<<<dim3(M_ / GBM, V_ / GBN), NT, GSMEM>>>(
        xchi, xclo, Ghi, Glo, out, nullptr, nullptr, gb, M_, V_, S2_);
}

// round 7
// speedup vs baseline: 1.2122x; 1.2104x over previous
#include <cuda_runtime.h>
#include <cuda_fp16.h>
#include <cstdint>

#define B_  2
#define L_  2048
#define D_  1024
#define S_  256
#define V_  32000
#define M_  (B_*L_)     /* 4096 */
#define S2_ (2*S_)      /* 512  */
#define EPS_ 1e-6f

#define CH_ 32
#define CL_ (L_/CH_)

// ---------------- scratch (__device__ globals; no allocs) ----------------
__device__ __align__(16) float g_ub [M_*S2_];    // packed [ubr | ubi]
__device__ __align__(16) float g_xc [M_*S2_];    // packed [xsr | xsi]
__device__ float g_endr[B_*CH_*S_];
__device__ float g_endi[B_*CH_*S_];
__device__ float g_incr[B_*CH_*S_];
__device__ float g_inci[B_*CH_*S_];
__device__ __align__(1024) __half g_uhi[M_*D_];
__device__ __align__(1024) __half g_ulo[M_*D_];
__device__ __align__(1024) __half g_bchi[D_*S2_];
__device__ __align__(1024) __half g_bclo[D_*S2_];
__device__ __align__(1024) __half g_xchi[M_*S2_];
__device__ __align__(1024) __half g_xclo[M_*S2_];
__device__ __align__(1024) __half g_cchi[S2_*D_];
__device__ __align__(1024) __half g_cclo[S2_*D_];
__device__ __align__(1024) __half g_whi[(size_t)D_*V_];
__device__ __align__(1024) __half g_wlo[(size_t)D_*V_];
__device__ __align__(1024) __half g_Ghi[(size_t)S2_*V_];
__device__ float g_gb[V_];

// ---------------- PTX helpers ------------------
__device__ __forceinline__ uint32_t smem_to_u32(const void* p) {
    uint32_t a;
    asm("{ .reg .u64 t; cvta.to.shared.u64 t, %1; cvt.u32.u64 %0, t; }"
        : "=r"(a) : "l"(p));
    return a;
}
__device__ __forceinline__ void cp_async16(uint32_t dst, const void* src) {
    asm volatile("cp.async.cg.shared.global [%0], [%1], 16;"
                 :: "r"(dst), "l"(src) : "memory");
}
#define CP_COMMIT() asm volatile("cp.async.commit_group;" ::: "memory")
#define CP_WAIT(n)  asm volatile("cp.async.wait_group %0;" :: "n"(n) : "memory")

#define LDSM4(r0,r1,r2,r3,a) \
    asm volatile("ldmatrix.sync.aligned.m8n8.x4.shared.b16 {%0,%1,%2,%3}, [%4];" \
        : "=r"(r0), "=r"(r1), "=r"(r2), "=r"(r3) : "r"(a))
#define LDSM4T(r0,r1,r2,r3,a) \
    asm volatile("ldmatrix.sync.aligned.m8n8.x4.trans.shared.b16 {%0,%1,%2,%3}, [%4];" \
        : "=r"(r0), "=r"(r1), "=r"(r2), "=r"(r3) : "r"(a))

#define MMA_F16(d, a0,a1,a2,a3, b0,b1) \
    asm volatile("mma.sync.aligned.m16n8k16.row.col.f32.f16.f16.f32 " \
        "{%0,%1,%2,%3}, {%4,%5,%6,%7}, {%8,%9}, {%0,%1,%2,%3};" \
        : "+f"((d)[0]), "+f"((d)[1]), "+f"((d)[2]), "+f"((d)[3]) \
        : "r"(a0), "r"(a1), "r"(a2), "r"(a3), "r"(b0), "r"(b1))

__inline__ __device__ float warpSum(float v) {
#pragma unroll
    for (int o = 16; o > 0; o >>= 1) v += __shfl_down_sync(0xffffffffu, v, o);
    return v;
}
__device__ __forceinline__ void split16(float v, __half& h, __half& l) {
    h = __float2half(v);
    l = __float2half(v - __half2float(h));
}

// =========================================================================
// embedding + double RMSNorm -> fp16 hi/lo
// =========================================================================
__global__ void embed_norm_kernel(const int* __restrict__ ids,
                                  const float* __restrict__ emb,
                                  const float* __restrict__ w1,
                                  const float* __restrict__ w2,
                                  __half* __restrict__ uhi,
                                  __half* __restrict__ ulo) {
    int token = blockIdx.x;
    int t = threadIdx.x;
    int id = ids[token];
    const float* e = emb + (size_t)id * D_;

    float v[4]; float ss = 0.f;
#pragma unroll
    for (int i = 0; i < 4; i++) { v[i] = e[t + 256 * i]; ss += v[i] * v[i]; }

    __shared__ float red[8];
    int lane = t & 31, wid = t >> 5;
    float w = warpSum(ss);
    if (lane == 0) red[wid] = w;
    __syncthreads();
    if (wid == 0) {
        float q = (lane < 8) ? red[lane] : 0.f;
        q = warpSum(q);
        if (lane == 0) red[0] = rsqrtf(q / (float)D_ + EPS_);
    }
    __syncthreads();
    float r1 = red[0];
    __syncthreads();

    float x[4]; float ss2 = 0.f;
#pragma unroll
    for (int i = 0; i < 4; i++) {
        x[i] = v[i] * r1 * w1[t + 256 * i];
        ss2 += x[i] * x[i];
    }
    float w2s = warpSum(ss2);
    if (lane == 0) red[wid] = w2s;
    __syncthreads();
    if (wid == 0) {
        float q = (lane < 8) ? red[lane] : 0.f;
        q = warpSum(q);
        if (lane == 0) red[0] = rsqrtf(q / (float)D_ + EPS_);
    }
    __syncthreads();
    float r2 = red[0];
#pragma unroll
    for (int i = 0; i < 4; i++) {
        float val = x[i] * r2 * w2[t + 256 * i];
        size_t o = (size_t)token * D_ + t + 256 * i;
        __half h, l; split16(val, h, l);
        uhi[o] = h; ulo[o] = l;
    }
}

// =========================================================================
// Chunked parallel complex scan
// =========================================================================
__global__ void scan_local_kernel(const float* __restrict__ Are,
                                  const float* __restrict__ Aim,
                                  const float* __restrict__ ub,
                                  float* __restrict__ xc,
                                  float* __restrict__ endr,
                                  float* __restrict__ endi) {
    int t = blockIdx.x * blockDim.x + threadIdx.x;
    int s = t % S_;
    int c = (t / S_) % CH_;
    int b = t / (S_ * CH_);
    float ar = Are[s], ai = Aim[s];
    float xr = 0.f, xi = 0.f;
    int tok0 = b * L_ + c * CL_;
    size_t base = (size_t)tok0 * S2_ + s;
    for (int j = 0; j < CL_; j++) {
        size_t o = base + (size_t)j * S2_;
        float ur = ub[o], ui = ub[o + S_];
        float nr = fmaf(ar, xr, fmaf(-ai, xi, ur));
        float ni = fmaf(ar, xi, fmaf(ai, xr, ui));
        xr = nr; xi = ni;
        xc[o] = xr; xc[o + S_] = xi;
    }
    endr[(b * CH_ + c) * S_ + s] = xr;
    endi[(b * CH_ + c) * S_ + s] = xi;
}

__global__ void scan_combine_kernel(const float* __restrict__ Are,
                                    const float* __restrict__ Aim,
                                    const float* __restrict__ endr,
                                    const float* __restrict__ endi,
                                    float* __restrict__ incr,
                                    float* __restrict__ inci) {
    int t = blockIdx.x * blockDim.x + threadIdx.x;
    if (t >= B_ * S_) return;
    int s = t % S_;
    int b = t / S_;
    float ar = Are[s], ai = Aim[s];
    float pr = 1.f, pi = 0.f;
    for (int j = 0; j < CL_; j++) {
        float nr = pr * ar - pi * ai;
        float ni = pr * ai + pi * ar;
        pr = nr; pi = ni;
    }
    float cr = 0.f, ci = 0.f;
    for (int c = 0; c < CH_; c++) {
        int idx = (b * CH_ + c) * S_ + s;
        incr[idx] = cr; inci[idx] = ci;
        float er = endr[idx], ei = endi[idx];
        float nr = fmaf(pr, cr, fmaf(-pi, ci, er));
        float ni = fmaf(pr, ci, fmaf(pi, cr, ei));
        cr = nr; ci = ni;
    }
}

__global__ void scan_fix_kernel(const float* __restrict__ Are,
                                const float* __restrict__ Aim,
                                const float* __restrict__ incr,
                                const float* __restrict__ inci,
                                const float* __restrict__ xc,
                                __half* __restrict__ xchi,
                                __half* __restrict__ xclo) {
    int t = blockIdx.x * blockDim.x + threadIdx.x;
    int s = t % S_;
    int c = (t / S_) % CH_;
    int b = t / (S_ * CH_);
    int cidx = (b * CH_ + c) * S_ + s;
    float x0r = incr[cidx], x0i = inci[cidx];
    float ar = Are[s], ai = Aim[s];
    float pr = ar, pi = ai;
    int tok0 = b * L_ + c * CL_;
    size_t base = (size_t)tok0 * S2_ + s;
    for (int j = 0; j < CL_; j++) {
        size_t o = base + (size_t)j * S2_;
        float vr = xc[o]      + (pr * x0r - pi * x0i);
        float vi = xc[o + S_] + (pr * x0i + pi * x0r);
        __half h, l;
        split16(vr, h, l); xchi[o] = h;       xclo[o] = l;
        split16(vi, h, l); xchi[o + S_] = h;  xclo[o + S_] = l;
        float nr = pr * ar - pi * ai;
        float ni = pr * ai + pi * ar;
        pr = nr; pi = ni;
    }
}

// =========================================================================
// converters
// =========================================================================
__global__ void ccat_kernel(const float* __restrict__ Cre,
                            const float* __restrict__ Cim,
                            __half* __restrict__ hi,
                            __half* __restrict__ lo) {
    int i = blockIdx.x * blockDim.x + threadIdx.x;
    int row = i >> 10;
    int d = i & 1023;
    float v = (row < S_) ? Cre[row * D_ + d] : -Cim[(row - S_) * D_ + d];
    __half h, l; split16(v, h, l);
    hi[i] = h; lo[i] = l;
}

__global__ void bcat_kernel(const float* __restrict__ Bre,
                            const float* __restrict__ Bim,
                            __half* __restrict__ hi,
                            __half* __restrict__ lo) {
    int i = blockIdx.x * blockDim.x + threadIdx.x;   // D_*S2_
    int d = i >> 9;
    int c = i & 511;
    float v = (c < S_) ? Bre[d * S_ + c] : Bim[d * S_ + (c - S_)];
    __half h, l; split16(v, h, l);
    hi[i] = h; lo[i] = l;
}

// vectorized: 4 vocab columns per thread
__global__ void wsplit_bias_kernel(const float* __restrict__ Hw,
                                   const float* __restrict__ Dp,
                                   const float* __restrict__ Hb,
                                   __half* __restrict__ whi,
                                   __half* __restrict__ wlo,
                                   float* __restrict__ gb) {
    int v4 = (blockIdx.x * blockDim.x + threadIdx.x) * 4;
    if (v4 >= V_) return;
    float a0 = 0.f, a1 = 0.f, a2 = 0.f, a3 = 0.f;
    for (int d = 0; d < D_; d++) {
        size_t o = (size_t)d * V_ + v4;
        float4 w = *(const float4*)(Hw + o);
        __half2 h01, h23, l01, l23;
        split16(w.x, h01.x, l01.x);
        split16(w.y, h01.y, l01.y);
        split16(w.z, h23.x, l23.x);
        split16(w.w, h23.y, l23.y);
        *(__half2*)(whi + o)     = h01;
        *(__half2*)(whi + o + 2) = h23;
        *(__half2*)(wlo + o)     = l01;
        *(__half2*)(wlo + o + 2) = l23;
        float dp = __ldg(Dp + d);
        a0 = fmaf(dp, w.x, a0); a1 = fmaf(dp, w.y, a1);
        a2 = fmaf(dp, w.z, a2); a3 = fmaf(dp, w.w, a3);
    }
    gb[v4]     = a0 + Hb[v4];
    gb[v4 + 1] = a1 + Hb[v4 + 1];
    gb[v4 + 2] = a2 + Hb[v4 + 2];
    gb[v4 + 3] = a3 + Hb[v4 + 3];
}

// =========================================================================
// Split-fp16 HMMA GEMM (round-4 structure). CTA 128x256, BK=32, 8 warps
// (2m x 4n, 64x64), 3-stage cp.async.
// USE_BLO=true : 3 terms (hihi + lohi + hilo), error ~2^-22  -> exact-ish
// USE_BLO=false: 2 terms (hihi + lohi), B hi-only, error ~2.8e-4
// =========================================================================
#define GBM 128
#define GBN 256
#define GBK 32
#define A_STRIDE 80                     /* (32+8)*2B per A row */
#define B_STRIDE 528                    /* (256+8)*2B per B row */
#define A_SPLIT  10240
#define A_TOT    20480
#define B_SPLIT  16896

template<bool USE_BLO>
__global__ __launch_bounds__(256, 1)
void mma_gemm(const __half* __restrict__ Ahi,
              const __half* __restrict__ Alo,
              const __half* __restrict__ Bhi,
              const __half* __restrict__ Blo,
              float* __restrict__ Cf,
              __half* __restrict__ Chi,
              const float* __restrict__ bias,
              int Mdim, int Ndim, int Kdim) {
    constexpr int STAGE_BYTES = A_TOT + (USE_BLO ? 2 * B_SPLIT : B_SPLIT);
    extern __shared__ char smem[];
    uint32_t sbase = smem_to_u32(smem);
    const int tid = threadIdx.x;
    const int lane = tid & 31, wid = tid >> 5;
    const int wm = wid & 1, wn = wid >> 1;          // 2 x 4 warps, 64x64 tile
    const int brow = blockIdx.x * GBM;
    const int bcol = blockIdx.y * GBN;
    const int lda = Kdim, ldb = Ndim;
    const int niter = Kdim / GBK;

    float acc[4][8][4];
#pragma unroll
    for (int i = 0; i < 4; i++)
#pragma unroll
        for (int j = 0; j < 8; j++)
#pragma unroll
            for (int k = 0; k < 4; k++) acc[i][j][k] = 0.f;

    auto load_stage = [&](int kt, int st) {
        const int k0 = kt * GBK;
        uint32_t sa = sbase + st * STAGE_BYTES;
#pragma unroll
        for (int i = 0; i < 2; i++) {                // A: 512 chunks/split
            int c = tid + i * 256;
            int r = c >> 2, ch = c & 3;
            uint32_t dst = sa + r * A_STRIDE + ch * 16;
            size_t src = (size_t)(brow + r) * lda + k0 + ch * 8;
            cp_async16(dst,           Ahi + src);
            cp_async16(dst + A_SPLIT, Alo + src);
        }
#pragma unroll
        for (int i = 0; i < 4; i++) {                // B: 1024 chunks/split
            int c = tid + i * 256;
            int r = c >> 5, ch = c & 31;
            uint32_t dst = sa + A_TOT + r * B_STRIDE + ch * 16;
            size_t src = (size_t)(k0 + r) * ldb + bcol + ch * 8;
            cp_async16(dst, Bhi + src);
            if (USE_BLO) cp_async16(dst + B_SPLIT, Blo + src);
        }
    };

    load_stage(0, 0); CP_COMMIT();
    load_stage(1, 1); CP_COMMIT();

    for (int kt = 0; kt < niter; kt++) {
        if (kt + 2 < niter) {
            load_stage(kt + 2, (kt + 2) % 3);
            CP_COMMIT();
            CP_WAIT(2);
        } else if (kt + 2 == niter) {
            CP_WAIT(1);
        } else {
            CP_WAIT(0);
        }
        __syncthreads();

        uint32_t sa = sbase + (kt % 3) * STAGE_BYTES;
#pragma unroll
        for (int ks = 0; ks < 2; ks++) {
            uint32_t ah[4][4], al[4][4];
#pragma unroll
            for (int mf = 0; mf < 4; mf++) {
                uint32_t addr = sa + (wm * 64 + mf * 16 + (lane & 15)) * A_STRIDE
                              + ks * 32 + (lane >> 4) * 16;
                LDSM4(ah[mf][0], ah[mf][1], ah[mf][2], ah[mf][3], addr);
                LDSM4(al[mf][0], al[mf][1], al[mf][2], al[mf][3], addr + A_SPLIT);
            }
            uint32_t bh[8][2], bl[8][2];
#pragma unroll
            for (int g = 0; g < 4; g++) {
                uint32_t addr = sa + A_TOT + (ks * 16 + (lane & 15)) * B_STRIDE
                              + (wn * 64 + g * 16 + (lane >> 4) * 8) * 2;
                uint32_t r0, r1, r2, r3;
                LDSM4T(r0, r1, r2, r3, addr);
                bh[2 * g][0] = r0; bh[2 * g][1] = r1;
                bh[2 * g + 1][0] = r2; bh[2 * g + 1][1] = r3;
                if (USE_BLO) {
                    LDSM4T(r0, r1, r2, r3, addr + B_SPLIT);
                    bl[2 * g][0] = r0; bl[2 * g][1] = r1;
                    bl[2 * g + 1][0] = r2; bl[2 * g + 1][1] = r3;
                }
            }
#pragma unroll
            for (int mf = 0; mf < 4; mf++)
#pragma unroll
                for (int nf = 0; nf < 8; nf++) {
                    MMA_F16(acc[mf][nf], ah[mf][0], ah[mf][1], ah[mf][2], ah[mf][3],
                            bh[nf][0], bh[nf][1]);
                    MMA_F16(acc[mf][nf], al[mf][0], al[mf][1], al[mf][2], al[mf][3],
                            bh[nf][0], bh[nf][1]);
                    if (USE_BLO)
                        MMA_F16(acc[mf][nf], ah[mf][0], ah[mf][1], ah[mf][2], ah[mf][3],
                                bl[nf][0], bl[nf][1]);
                }
        }
        __syncthreads();
    }

    if (Chi) {
        // fp16-hi epilogue (lo not needed downstream)
#pragma unroll
        for (int mf = 0; mf < 4; mf++) {
            int r0 = brow + wm * 64 + mf * 16 + (lane >> 2);
#pragma unroll
            for (int nf = 0; nf < 8; nf++) {
                int c0 = bcol + wn * 64 + nf * 8 + (lane & 3) * 2;
#pragma unroll
                for (int half_ = 0; half_ < 2; half_++) {
                    __half2 hv;
                    hv.x = __float2half(acc[mf][nf][2 * half_]);
                    hv.y = __float2half(acc[mf][nf][2 * half_ + 1]);
                    *(__half2*)(Chi + (size_t)(r0 + 8 * half_) * Ndim + c0) = hv;
                }
            }
        }
    } else {
#pragma unroll
        for (int mf = 0; mf < 4; mf++) {
            int r0 = brow + wm * 64 + mf * 16 + (lane >> 2);
#pragma unroll
            for (int nf = 0; nf < 8; nf++) {
                int c0 = bcol + wn * 64 + nf * 8 + (lane & 3) * 2;
                float b0 = 0.f, b1 = 0.f;
                if (bias) { b0 = __ldg(bias + c0); b1 = __ldg(bias + c0 + 1); }
                float2 v0 = make_float2(acc[mf][nf][0] + b0, acc[mf][nf][1] + b1);
                float2 v1 = make_float2(acc[mf][nf][2] + b0, acc[mf][nf][3] + b1);
                *(float2*)(Cf + (size_t)r0 * Ndim + c0)       = v0;
                *(float2*)(Cf + (size_t)(r0 + 8) * Ndim + c0) = v1;
            }
        }
    }
}

// =========================================================================
extern "C" void kernel_launch(void* const* d_in, const int* in_sizes, int n_in,
                              void* d_out, int out_size) {
    const int*   ids = (const int*)  d_in[0];
    const float* emb = (const float*)d_in[1];
    const float* w1  = (const float*)d_in[2];
    const float* w2  = (const float*)d_in[3];
    const float* Are = (const float*)d_in[4];
    const float* Aim = (const float*)d_in[5];
    const float* Bre = (const float*)d_in[6];
    const float* Bim = (const float*)d_in[7];
    const float* Cre = (const float*)d_in[8];
    const float* Cim = (const float*)d_in[9];
    const float* Dp  = (const float*)d_in[10];
    const float* Hw  = (const float*)d_in[11];
    const float* Hb  = (const float*)d_in[12];
    float* out = (float*)d_out;

    float *ub, *xc, *endr, *endi, *incr, *inci, *gb;
    __half *uhi, *ulo, *bchi, *bclo, *xchi, *xclo;
    __half *cchi, *cclo, *whi, *wlo, *Ghi;
    cudaGetSymbolAddress((void**)&ub,   g_ub);
    cudaGetSymbolAddress((void**)&xc,   g_xc);
    cudaGetSymbolAddress((void**)&endr, g_endr);
    cudaGetSymbolAddress((void**)&endi, g_endi);
    cudaGetSymbolAddress((void**)&incr, g_incr);
    cudaGetSymbolAddress((void**)&inci, g_inci);
    cudaGetSymbolAddress((void**)&uhi,  g_uhi);
    cudaGetSymbolAddress((void**)&ulo,  g_ulo);
    cudaGetSymbolAddress((void**)&bchi, g_bchi);
    cudaGetSymbolAddress((void**)&bclo, g_bclo);
    cudaGetSymbolAddress((void**)&xchi, g_xchi);
    cudaGetSymbolAddress((void**)&xclo, g_xclo);
    cudaGetSymbolAddress((void**)&cchi, g_cchi);
    cudaGetSymbolAddress((void**)&cclo, g_cclo);
    cudaGetSymbolAddress((void**)&whi,  g_whi);
    cudaGetSymbolAddress((void**)&wlo,  g_wlo);
    cudaGetSymbolAddress((void**)&Ghi,  g_Ghi);
    cudaGetSymbolAddress((void**)&gb,   g_gb);

    const int SM3 = 3 * (A_TOT + 2 * B_SPLIT);   // 162816 (3-term)
    const int SM2 = 3 * (A_TOT + B_SPLIT);       // 112128 (2-term)
    cudaFuncSetAttribute(mma_gemm<true>,
                         cudaFuncAttributeMaxDynamicSharedMemorySize, SM3);
    cudaFuncSetAttribute(mma_gemm<false>,
                         cudaFuncAttributeMaxDynamicSharedMemorySize, SM2);

    // ---- weight prep ----
    wsplit_bias_kernel<<<(V_ / 4 + 255) / 256, 256>>>(Hw, Dp, Hb, whi, wlo, gb);
    ccat_kernel<<<(S2_ * D_) / 256, 256>>>(Cre, Cim, cchi, cclo);
    bcat_kernel<<<(D_ * S2_) / 256, 256>>>(Bre, Bim, bchi, bclo);

    // G = Ccat @ Hw  [512, 32000]  (3-term exact; epilogue -> Ghi fp16)
    mma_gemm<true><<<dim3(S2_ / GBM, V_ / GBN), 256, SM3>>>(
        cchi, cclo, whi, wlo, nullptr, Ghi, nullptr, S2_, V_, D_);

    // ---- activation chain ----
    embed_norm_kernel<<<M_, 256>>>(ids, emb, w1, w2, uhi, ulo);

    // uB = u @ Bcat  [4096, 512]  (3-term exact, fp32 out)
    mma_gemm<true><<<dim3(M_ / GBM, S2_ / GBN), 256, SM3>>>(
        uhi, ulo, bchi, bclo, ub, nullptr, nullptr, M_, S2_, D_);

    // parallel complex scan -> xchi/xclo
    scan_local_kernel<<<(B_ * CH_ * S_) / 256, 256>>>(Are, Aim, ub, xc, endr, endi);
    scan_combine_kernel<<<(B_ * S_ + 255) / 256, 256>>>(Are, Aim, endr, endi, incr, inci);
    scan_fix_kernel<<<(B_ * CH_ * S_) / 256, 256>>>(Are, Aim, incr, inci, xc, xchi, xclo);

    // logits = xc @ G + gb  [4096, 32000]  (2-term, B = Ghi only)
    mma_gemm<false><<<dim3(M_ / GBM, V_ / GBN), 256, SM2>>>(
        xchi, xclo, Ghi, nullptr, out, nullptr, gb, M_, V_, S2_);
}

// round 8
// speedup vs baseline: 1.7025x; 1.4044x over previous
#include <cuda_runtime.h>
#include <cuda_fp16.h>
#include <cstdint>

#define B_  2
#define L_  2048
#define D_  1024
#define S_  256
#define V_  32000
#define M_  (B_*L_)     /* 4096 */
#define S2_ (2*S_)      /* 512  */
#define EPS_ 1e-6f

#define CH_ 32
#define CL_ (L_/CH_)

// ---------------- scratch (__device__ globals; no allocs) ----------------
__device__ __align__(16) float g_ub [M_*S2_];    // packed [ubr | ubi]
__device__ __align__(16) float g_xc [M_*S2_];    // packed [xsr | xsi]
__device__ float g_endr[B_*CH_*S_];
__device__ float g_endi[B_*CH_*S_];
__device__ float g_incr[B_*CH_*S_];
__device__ float g_inci[B_*CH_*S_];
__device__ __align__(1024) __half g_uhi[M_*D_];
__device__ __align__(1024) __half g_ulo[M_*D_];
__device__ __align__(1024) __half g_bchi[D_*S2_];
__device__ __align__(1024) __half g_bclo[D_*S2_];
__device__ __align__(1024) __half g_xchi[M_*S2_];
__device__ __align__(1024) __half g_cchi[S2_*D_];
__device__ __align__(1024) __half g_cclo[S2_*D_];
__device__ __align__(1024) __half g_whi[(size_t)D_*V_];
__device__ __align__(1024) __half g_Ghi[(size_t)S2_*V_];
__device__ float g_gb[V_];

// ---------------- PTX helpers ------------------
__device__ __forceinline__ uint32_t smem_to_u32(const void* p) {
    uint32_t a;
    asm("{ .reg .u64 t; cvta.to.shared.u64 t, %1; cvt.u32.u64 %0, t; }"
        : "=r"(a) : "l"(p));
    return a;
}
__device__ __forceinline__ void cp_async16(uint32_t dst, const void* src) {
    asm volatile("cp.async.cg.shared.global [%0], [%1], 16;"
                 :: "r"(dst), "l"(src) : "memory");
}
#define CP_COMMIT() asm volatile("cp.async.commit_group;" ::: "memory")
#define CP_WAIT(n)  asm volatile("cp.async.wait_group %0;" :: "n"(n) : "memory")

#define LDSM4(r0,r1,r2,r3,a) \
    asm volatile("ldmatrix.sync.aligned.m8n8.x4.shared.b16 {%0,%1,%2,%3}, [%4];" \
        : "=r"(r0), "=r"(r1), "=r"(r2), "=r"(r3) : "r"(a))
#define LDSM4T(r0,r1,r2,r3,a) \
    asm volatile("ldmatrix.sync.aligned.m8n8.x4.trans.shared.b16 {%0,%1,%2,%3}, [%4];" \
        : "=r"(r0), "=r"(r1), "=r"(r2), "=r"(r3) : "r"(a))

#define MMA_F16(d, a0,a1,a2,a3, b0,b1) \
    asm volatile("mma.sync.aligned.m16n8k16.row.col.f32.f16.f16.f32 " \
        "{%0,%1,%2,%3}, {%4,%5,%6,%7}, {%8,%9}, {%0,%1,%2,%3};" \
        : "+f"((d)[0]), "+f"((d)[1]), "+f"((d)[2]), "+f"((d)[3]) \
        : "r"(a0), "r"(a1), "r"(a2), "r"(a3), "r"(b0), "r"(b1))

__inline__ __device__ float warpSum(float v) {
#pragma unroll
    for (int o = 16; o > 0; o >>= 1) v += __shfl_down_sync(0xffffffffu, v, o);
    return v;
}
__device__ __forceinline__ void split16(float v, __half& h, __half& l) {
    h = __float2half(v);
    l = __float2half(v - __half2float(h));
}

// =========================================================================
// embedding + double RMSNorm -> fp16 hi/lo
// =========================================================================
__global__ void embed_norm_kernel(const int* __restrict__ ids,
                                  const float* __restrict__ emb,
                                  const float* __restrict__ w1,
                                  const float* __restrict__ w2,
                                  __half* __restrict__ uhi,
                                  __half* __restrict__ ulo) {
    int token = blockIdx.x;
    int t = threadIdx.x;
    int id = ids[token];
    const float* e = emb + (size_t)id * D_;

    float v[4]; float ss = 0.f;
#pragma unroll
    for (int i = 0; i < 4; i++) { v[i] = e[t + 256 * i]; ss += v[i] * v[i]; }

    __shared__ float red[8];
    int lane = t & 31, wid = t >> 5;
    float w = warpSum(ss);
    if (lane == 0) red[wid] = w;
    __syncthreads();
    if (wid == 0) {
        float q = (lane < 8) ? red[lane] : 0.f;
        q = warpSum(q);
        if (lane == 0) red[0] = rsqrtf(q / (float)D_ + EPS_);
    }
    __syncthreads();
    float r1 = red[0];
    __syncthreads();

    float x[4]; float ss2 = 0.f;
#pragma unroll
    for (int i = 0; i < 4; i++) {
        x[i] = v[i] * r1 * w1[t + 256 * i];
        ss2 += x[i] * x[i];
    }
    float w2s = warpSum(ss2);
    if (lane == 0) red[wid] = w2s;
    __syncthreads();
    if (wid == 0) {
        float q = (lane < 8) ? red[lane] : 0.f;
        q = warpSum(q);
        if (lane == 0) red[0] = rsqrtf(q / (float)D_ + EPS_);
    }
    __syncthreads();
    float r2 = red[0];
#pragma unroll
    for (int i = 0; i < 4; i++) {
        float val = x[i] * r2 * w2[t + 256 * i];
        size_t o = (size_t)token * D_ + t + 256 * i;
        __half h, l; split16(val, h, l);
        uhi[o] = h; ulo[o] = l;
    }
}

// =========================================================================
// Chunked parallel complex scan
// =========================================================================
__global__ void scan_local_kernel(const float* __restrict__ Are,
                                  const float* __restrict__ Aim,
                                  const float* __restrict__ ub,
                                  float* __restrict__ xc,
                                  float* __restrict__ endr,
                                  float* __restrict__ endi) {
    int t = blockIdx.x * blockDim.x + threadIdx.x;
    int s = t % S_;
    int c = (t / S_) % CH_;
    int b = t / (S_ * CH_);
    float ar = Are[s], ai = Aim[s];
    float xr = 0.f, xi = 0.f;
    int tok0 = b * L_ + c * CL_;
    size_t base = (size_t)tok0 * S2_ + s;
    for (int j = 0; j < CL_; j++) {
        size_t o = base + (size_t)j * S2_;
        float ur = ub[o], ui = ub[o + S_];
        float nr = fmaf(ar, xr, fmaf(-ai, xi, ur));
        float ni = fmaf(ar, xi, fmaf(ai, xr, ui));
        xr = nr; xi = ni;
        xc[o] = xr; xc[o + S_] = xi;
    }
    endr[(b * CH_ + c) * S_ + s] = xr;
    endi[(b * CH_ + c) * S_ + s] = xi;
}

__global__ void scan_combine_kernel(const float* __restrict__ Are,
                                    const float* __restrict__ Aim,
                                    const float* __restrict__ endr,
                                    const float* __restrict__ endi,
                                    float* __restrict__ incr,
                                    float* __restrict__ inci) {
    int t = blockIdx.x * blockDim.x + threadIdx.x;
    if (t >= B_ * S_) return;
    int s = t % S_;
    int b = t / S_;
    float ar = Are[s], ai = Aim[s];
    float pr = 1.f, pi = 0.f;
    for (int j = 0; j < CL_; j++) {
        float nr = pr * ar - pi * ai;
        float ni = pr * ai + pi * ar;
        pr = nr; pi = ni;
    }
    float cr = 0.f, ci = 0.f;
    for (int c = 0; c < CH_; c++) {
        int idx = (b * CH_ + c) * S_ + s;
        incr[idx] = cr; inci[idx] = ci;
        float er = endr[idx], ei = endi[idx];
        float nr = fmaf(pr, cr, fmaf(-pi, ci, er));
        float ni = fmaf(pr, ci, fmaf(pi, cr, ei));
        cr = nr; ci = ni;
    }
}

__global__ void scan_fix_kernel(const float* __restrict__ Are,
                                const float* __restrict__ Aim,
                                const float* __restrict__ incr,
                                const float* __restrict__ inci,
                                const float* __restrict__ xc,
                                __half* __restrict__ xchi) {
    int t = blockIdx.x * blockDim.x + threadIdx.x;
    int s = t % S_;
    int c = (t / S_) % CH_;
    int b = t / (S_ * CH_);
    int cidx = (b * CH_ + c) * S_ + s;
    float x0r = incr[cidx], x0i = inci[cidx];
    float ar = Are[s], ai = Aim[s];
    float pr = ar, pi = ai;
    int tok0 = b * L_ + c * CL_;
    size_t base = (size_t)tok0 * S2_ + s;
    for (int j = 0; j < CL_; j++) {
        size_t o = base + (size_t)j * S2_;
        float vr = xc[o]      + (pr * x0r - pi * x0i);
        float vi = xc[o + S_] + (pr * x0i + pi * x0r);
        xchi[o]      = __float2half(vr);
        xchi[o + S_] = __float2half(vi);
        float nr = pr * ar - pi * ai;
        float ni = pr * ai + pi * ar;
        pr = nr; pi = ni;
    }
}

// =========================================================================
// converters
// =========================================================================
__global__ void ccat_kernel(const float* __restrict__ Cre,
                            const float* __restrict__ Cim,
                            __half* __restrict__ hi,
                            __half* __restrict__ lo) {
    int i = blockIdx.x * blockDim.x + threadIdx.x;
    int row = i >> 10;
    int d = i & 1023;
    float v = (row < S_) ? Cre[row * D_ + d] : -Cim[(row - S_) * D_ + d];
    __half h, l; split16(v, h, l);
    hi[i] = h; lo[i] = l;
}

__global__ void bcat_kernel(const float* __restrict__ Bre,
                            const float* __restrict__ Bim,
                            __half* __restrict__ hi,
                            __half* __restrict__ lo) {
    int i = blockIdx.x * blockDim.x + threadIdx.x;   // D_*S2_
    int d = i >> 9;
    int c = i & 511;
    float v = (c < S_) ? Bre[d * S_ + c] : Bim[d * S_ + (c - S_)];
    __half h, l; split16(v, h, l);
    hi[i] = h; lo[i] = l;
}

// fp16-hi only + gb reduction; 4 vocab columns per thread
__global__ void wsplit_bias_kernel(const float* __restrict__ Hw,
                                   const float* __restrict__ Dp,
                                   const float* __restrict__ Hb,
                                   __half* __restrict__ whi,
                                   float* __restrict__ gb) {
    int v4 = (blockIdx.x * blockDim.x + threadIdx.x) * 4;
    if (v4 >= V_) return;
    float a0 = 0.f, a1 = 0.f, a2 = 0.f, a3 = 0.f;
    for (int d = 0; d < D_; d++) {
        size_t o = (size_t)d * V_ + v4;
        float4 w = *(const float4*)(Hw + o);
        __half2 h01, h23;
        h01.x = __float2half(w.x); h01.y = __float2half(w.y);
        h23.x = __float2half(w.z); h23.y = __float2half(w.w);
        *(__half2*)(whi + o)     = h01;
        *(__half2*)(whi + o + 2) = h23;
        float dp = __ldg(Dp + d);
        a0 = fmaf(dp, w.x, a0); a1 = fmaf(dp, w.y, a1);
        a2 = fmaf(dp, w.z, a2); a3 = fmaf(dp, w.w, a3);
    }
    gb[v4]     = a0 + Hb[v4];
    gb[v4 + 1] = a1 + Hb[v4 + 1];
    gb[v4 + 2] = a2 + Hb[v4 + 2];
    gb[v4 + 3] = a3 + Hb[v4 + 3];
}

// =========================================================================
// Split-fp16 HMMA GEMM. CTA 128x256, BK=32, 8 warps (2m x 4n), 3-stage.
// TERMS=3: AhiBhi + AloBhi + AhiBlo  (exact)
// TERMS=2: AhiBhi + AloBhi           (B hi only)
// TERMS=1: AhiBhi                    (both hi only)
// =========================================================================
#define GBM 128
#define GBN 256
#define GBK 32
#define A_STRIDE 80
#define B_STRIDE 528
#define A_SPLIT  10240
#define B_SPLIT  16896

template<int TERMS>
__global__ __launch_bounds__(256, 1)
void mma_gemm(const __half* __restrict__ Ahi,
              const __half* __restrict__ Alo,
              const __half* __restrict__ Bhi,
              const __half* __restrict__ Blo,
              float* __restrict__ Cf,
              __half* __restrict__ Chi,
              const float* __restrict__ bias,
              int Mdim, int Ndim, int Kdim) {
    constexpr int A_BYTES = (TERMS >= 2) ? 2 * A_SPLIT : A_SPLIT;
    constexpr int STAGE_BYTES = A_BYTES + ((TERMS == 3) ? 2 * B_SPLIT : B_SPLIT);
    extern __shared__ char smem[];
    uint32_t sbase = smem_to_u32(smem);
    const int tid = threadIdx.x;
    const int lane = tid & 31, wid = tid >> 5;
    const int wm = wid & 1, wn = wid >> 1;
    const int brow = blockIdx.x * GBM;
    const int bcol = blockIdx.y * GBN;
    const int lda = Kdim, ldb = Ndim;
    const int niter = Kdim / GBK;

    float acc[4][8][4];
#pragma unroll
    for (int i = 0; i < 4; i++)
#pragma unroll
        for (int j = 0; j < 8; j++)
#pragma unroll
            for (int k = 0; k < 4; k++) acc[i][j][k] = 0.f;

    auto load_stage = [&](int kt, int st) {
        const int k0 = kt * GBK;
        uint32_t sa = sbase + st * STAGE_BYTES;
#pragma unroll
        for (int i = 0; i < 2; i++) {                // A: 512 chunks per split
            int c = tid + i * 256;
            int r = c >> 2, ch = c & 3;
            uint32_t dst = sa + r * A_STRIDE + ch * 16;
            size_t src = (size_t)(brow + r) * lda + k0 + ch * 8;
            cp_async16(dst, Ahi + src);
            if (TERMS >= 2) cp_async16(dst + A_SPLIT, Alo + src);
        }
#pragma unroll
        for (int i = 0; i < 4; i++) {                // B: 1024 chunks per split
            int c = tid + i * 256;
            int r = c >> 5, ch = c & 31;
            uint32_t dst = sa + A_BYTES + r * B_STRIDE + ch * 16;
            size_t src = (size_t)(k0 + r) * ldb + bcol + ch * 8;
            cp_async16(dst, Bhi + src);
            if (TERMS == 3) cp_async16(dst + B_SPLIT, Blo + src);
        }
    };

    load_stage(0, 0); CP_COMMIT();
    load_stage(1, 1); CP_COMMIT();

    for (int kt = 0; kt < niter; kt++) {
        if (kt + 2 < niter) {
            load_stage(kt + 2, (kt + 2) % 3);
            CP_COMMIT();
            CP_WAIT(2);
        } else if (kt + 2 == niter) {
            CP_WAIT(1);
        } else {
            CP_WAIT(0);
        }
        __syncthreads();

        uint32_t sa = sbase + (kt % 3) * STAGE_BYTES;
#pragma unroll
        for (int ks = 0; ks < 2; ks++) {
            uint32_t ah[4][4], al[4][4];
#pragma unroll
            for (int mf = 0; mf < 4; mf++) {
                uint32_t addr = sa + (wm * 64 + mf * 16 + (lane & 15)) * A_STRIDE
                              + ks * 32 + (lane >> 4) * 16;
                LDSM4(ah[mf][0], ah[mf][1], ah[mf][2], ah[mf][3], addr);
                if (TERMS >= 2)
                    LDSM4(al[mf][0], al[mf][1], al[mf][2], al[mf][3], addr + A_SPLIT);
            }
            uint32_t bh[8][2], bl[8][2];
#pragma unroll
            for (int g = 0; g < 4; g++) {
                uint32_t addr = sa + A_BYTES + (ks * 16 + (lane & 15)) * B_STRIDE
                              + (wn * 64 + g * 16 + (lane >> 4) * 8) * 2;
                uint32_t r0, r1, r2, r3;
                LDSM4T(r0, r1, r2, r3, addr);
                bh[2 * g][0] = r0; bh[2 * g][1] = r1;
                bh[2 * g + 1][0] = r2; bh[2 * g + 1][1] = r3;
                if (TERMS == 3) {
                    LDSM4T(r0, r1, r2, r3, addr + B_SPLIT);
                    bl[2 * g][0] = r0; bl[2 * g][1] = r1;
                    bl[2 * g + 1][0] = r2; bl[2 * g + 1][1] = r3;
                }
            }
#pragma unroll
            for (int mf = 0; mf < 4; mf++)
#pragma unroll
                for (int nf = 0; nf < 8; nf++) {
                    MMA_F16(acc[mf][nf], ah[mf][0], ah[mf][1], ah[mf][2], ah[mf][3],
                            bh[nf][0], bh[nf][1]);
                    if (TERMS >= 2)
                        MMA_F16(acc[mf][nf], al[mf][0], al[mf][1], al[mf][2], al[mf][3],
                                bh[nf][0], bh[nf][1]);
                    if (TERMS == 3)
                        MMA_F16(acc[mf][nf], ah[mf][0], ah[mf][1], ah[mf][2], ah[mf][3],
                                bl[nf][0], bl[nf][1]);
                }
        }
        __syncthreads();
    }

    if (Chi) {
#pragma unroll
        for (int mf = 0; mf < 4; mf++) {
            int r0 = brow + wm * 64 + mf * 16 + (lane >> 2);
#pragma unroll
            for (int nf = 0; nf < 8; nf++) {
                int c0 = bcol + wn * 64 + nf * 8 + (lane & 3) * 2;
#pragma unroll
                for (int half_ = 0; half_ < 2; half_++) {
                    __half2 hv;
                    hv.x = __float2half(acc[mf][nf][2 * half_]);
                    hv.y = __float2half(acc[mf][nf][2 * half_ + 1]);
                    *(__half2*)(Chi + (size_t)(r0 + 8 * half_) * Ndim + c0) = hv;
                }
            }
        }
    } else {
#pragma unroll
        for (int mf = 0; mf < 4; mf++) {
            int r0 = brow + wm * 64 + mf * 16 + (lane >> 2);
#pragma unroll
            for (int nf = 0; nf < 8; nf++) {
                int c0 = bcol + wn * 64 + nf * 8 + (lane & 3) * 2;
                float b0 = 0.f, b1 = 0.f;
                if (bias) { b0 = __ldg(bias + c0); b1 = __ldg(bias + c0 + 1); }
                float2 v0 = make_float2(acc[mf][nf][0] + b0, acc[mf][nf][1] + b1);
                float2 v1 = make_float2(acc[mf][nf][2] + b0, acc[mf][nf][3] + b1);
                *(float2*)(Cf + (size_t)r0 * Ndim + c0)       = v0;
                *(float2*)(Cf + (size_t)(r0 + 8) * Ndim + c0) = v1;
            }
        }
    }
}

// =========================================================================
extern "C" void kernel_launch(void* const* d_in, const int* in_sizes, int n_in,
                              void* d_out, int out_size) {
    const int*   ids = (const int*)  d_in[0];
    const float* emb = (const float*)d_in[1];
    const float* w1  = (const float*)d_in[2];
    const float* w2  = (const float*)d_in[3];
    const float* Are = (const float*)d_in[4];
    const float* Aim = (const float*)d_in[5];
    const float* Bre = (const float*)d_in[6];
    const float* Bim = (const float*)d_in[7];
    const float* Cre = (const float*)d_in[8];
    const float* Cim = (const float*)d_in[9];
    const float* Dp  = (const float*)d_in[10];
    const float* Hw  = (const float*)d_in[11];
    const float* Hb  = (const float*)d_in[12];
    float* out = (float*)d_out;

    float *ub, *xc, *endr, *endi, *incr, *inci, *gb;
    __half *uhi, *ulo, *bchi, *bclo, *xchi;
    __half *cchi, *cclo, *whi, *Ghi;
    cudaGetSymbolAddress((void**)&ub,   g_ub);
    cudaGetSymbolAddress((void**)&xc,   g_xc);
    cudaGetSymbolAddress((void**)&endr, g_endr);
    cudaGetSymbolAddress((void**)&endi, g_endi);
    cudaGetSymbolAddress((void**)&incr, g_incr);
    cudaGetSymbolAddress((void**)&inci, g_inci);
    cudaGetSymbolAddress((void**)&uhi,  g_uhi);
    cudaGetSymbolAddress((void**)&ulo,  g_ulo);
    cudaGetSymbolAddress((void**)&bchi, g_bchi);
    cudaGetSymbolAddress((void**)&bclo, g_bclo);
    cudaGetSymbolAddress((void**)&xchi, g_xchi);
    cudaGetSymbolAddress((void**)&cchi, g_cchi);
    cudaGetSymbolAddress((void**)&cclo, g_cclo);
    cudaGetSymbolAddress((void**)&whi,  g_whi);
    cudaGetSymbolAddress((void**)&Ghi,  g_Ghi);
    cudaGetSymbolAddress((void**)&gb,   g_gb);

    const int SM3 = 3 * (2 * A_SPLIT + 2 * B_SPLIT);  // 162816
    const int SM2 = 3 * (2 * A_SPLIT + B_SPLIT);      // 112128
    const int SM1 = 3 * (A_SPLIT + B_SPLIT);          // 81408
    cudaFuncSetAttribute(mma_gemm<3>,
                         cudaFuncAttributeMaxDynamicSharedMemorySize, SM3);
    cudaFuncSetAttribute(mma_gemm<2>,
                         cudaFuncAttributeMaxDynamicSharedMemorySize, SM2);
    cudaFuncSetAttribute(mma_gemm<1>,
                         cudaFuncAttributeMaxDynamicSharedMemorySize, SM1);

    // ---- weight prep ----
    wsplit_bias_kernel<<<(V_ / 4 + 255) / 256, 256>>>(Hw, Dp, Hb, whi, gb);
    ccat_kernel<<<(S2_ * D_) / 256, 256>>>(Cre, Cim, cchi, cclo);
    bcat_kernel<<<(D_ * S2_) / 256, 256>>>(Bre, Bim, bchi, bclo);

    // G = Ccat @ Hw  [512, 32000]  (2-term; B = whi only; epilogue fp16)
    mma_gemm<2><<<dim3(S2_ / GBM, V_ / GBN), 256, SM2>>>(
        cchi, cclo, whi, nullptr, nullptr, Ghi, nullptr, S2_, V_, D_);

    // ---- activation chain ----
    embed_norm_kernel<<<M_, 256>>>(ids, emb, w1, w2, uhi, ulo);

    // uB = u @ Bcat  [4096, 512]  (3-term exact, fp32 out)
    mma_gemm<3><<<dim3(M_ / GBM, S2_ / GBN), 256, SM3>>>(
        uhi, ulo, bchi, bclo, ub, nullptr, nullptr, M_, S2_, D_);

    // parallel complex scan -> xchi (fp16)
    scan_local_kernel<<<(B_ * CH_ * S_) / 256, 256>>>(Are, Aim, ub, xc, endr, endi);
    scan_combine_kernel<<<(B_ * S_ + 255) / 256, 256>>>(Are, Aim, endr, endi, incr, inci);
    scan_fix_kernel<<<(B_ * CH_ * S_) / 256, 256>>>(Are, Aim, incr, inci, xc, xchi);

    // logits = xchi @ Ghi + gb  [4096, 32000]  (1-term pure fp16)
    mma_gemm<1><<<dim3(M_ / GBM, V_ / GBN), 256, SM1>>>(
        xchi, nullptr, Ghi, nullptr, out, nullptr, gb, M_, V_, S2_);
}

// round 9
// speedup vs baseline: 1.9901x; 1.1689x over previous
#include <cuda_runtime.h>
#include <cuda_fp16.h>
#include <cstdint>

#define B_  2
#define L_  2048
#define D_  1024
#define S_  256
#define V_  32000
#define M_  (B_*L_)     /* 4096 */
#define S2_ (2*S_)      /* 512  */
#define EPS_ 1e-6f

#define CH_ 128
#define CL_ (L_/CH_)    /* 16 */
#define GB_SLICES 16    /* D_/64 slices for the gb GEMV */

// ---------------- scratch (__device__ globals; no allocs) ----------------
__device__ __align__(16) float g_ub [M_*S2_];    // packed [ubr | ubi]
__device__ float g_endr[B_*CH_*S_];
__device__ float g_endi[B_*CH_*S_];
__device__ float g_incr[B_*CH_*S_];
__device__ float g_inci[B_*CH_*S_];
__device__ float g_gpart[GB_SLICES*V_];
__device__ __align__(1024) __half g_uhi[M_*D_];
__device__ __align__(1024) __half g_ulo[M_*D_];
__device__ __align__(1024) __half g_bchi[D_*S2_];
__device__ __align__(1024) __half g_bclo[D_*S2_];
__device__ __align__(1024) __half g_xchi[M_*S2_];
__device__ __align__(1024) __half g_cchi[S2_*D_];
__device__ __align__(1024) __half g_cclo[S2_*D_];
__device__ __align__(1024) __half g_whi[(size_t)D_*V_];
__device__ __align__(1024) __half g_Ghi[(size_t)S2_*V_];
__device__ float g_gb[V_];

// ---------------- PTX helpers ------------------
__device__ __forceinline__ uint32_t smem_to_u32(const void* p) {
    uint32_t a;
    asm("{ .reg .u64 t; cvta.to.shared.u64 t, %1; cvt.u32.u64 %0, t; }"
        : "=r"(a) : "l"(p));
    return a;
}
__device__ __forceinline__ void cp_async16(uint32_t dst, const void* src) {
    asm volatile("cp.async.cg.shared.global [%0], [%1], 16;"
                 :: "r"(dst), "l"(src) : "memory");
}
#define CP_COMMIT() asm volatile("cp.async.commit_group;" ::: "memory")
#define CP_WAIT(n)  asm volatile("cp.async.wait_group %0;" :: "n"(n) : "memory")

#define LDSM4(r0,r1,r2,r3,a) \
    asm volatile("ldmatrix.sync.aligned.m8n8.x4.shared.b16 {%0,%1,%2,%3}, [%4];" \
        : "=r"(r0), "=r"(r1), "=r"(r2), "=r"(r3) : "r"(a))
#define LDSM4T(r0,r1,r2,r3,a) \
    asm volatile("ldmatrix.sync.aligned.m8n8.x4.trans.shared.b16 {%0,%1,%2,%3}, [%4];" \
        : "=r"(r0), "=r"(r1), "=r"(r2), "=r"(r3) : "r"(a))

#define MMA_F16(d, a0,a1,a2,a3, b0,b1) \
    asm volatile("mma.sync.aligned.m16n8k16.row.col.f32.f16.f16.f32 " \
        "{%0,%1,%2,%3}, {%4,%5,%6,%7}, {%8,%9}, {%0,%1,%2,%3};" \
        : "+f"((d)[0]), "+f"((d)[1]), "+f"((d)[2]), "+f"((d)[3]) \
        : "r"(a0), "r"(a1), "r"(a2), "r"(a3), "r"(b0), "r"(b1))

__inline__ __device__ float warpSum(float v) {
#pragma unroll
    for (int o = 16; o > 0; o >>= 1) v += __shfl_down_sync(0xffffffffu, v, o);
    return v;
}
__device__ __forceinline__ void split16(float v, __half& h, __half& l) {
    h = __float2half(v);
    l = __float2half(v - __half2float(h));
}

// =========================================================================
// embedding + double RMSNorm -> fp16 hi/lo
// =========================================================================
__global__ void embed_norm_kernel(const int* __restrict__ ids,
                                  const float* __restrict__ emb,
                                  const float* __restrict__ w1,
                                  const float* __restrict__ w2,
                                  __half* __restrict__ uhi,
                                  __half* __restrict__ ulo) {
    int token = blockIdx.x;
    int t = threadIdx.x;
    int id = ids[token];
    const float* e = emb + (size_t)id * D_;

    float v[4]; float ss = 0.f;
#pragma unroll
    for (int i = 0; i < 4; i++) { v[i] = e[t + 256 * i]; ss += v[i] * v[i]; }

    __shared__ float red[8];
    int lane = t & 31, wid = t >> 5;
    float w = warpSum(ss);
    if (lane == 0) red[wid] = w;
    __syncthreads();
    if (wid == 0) {
        float q = (lane < 8) ? red[lane] : 0.f;
        q = warpSum(q);
        if (lane == 0) red[0] = rsqrtf(q / (float)D_ + EPS_);
    }
    __syncthreads();
    float r1 = red[0];
    __syncthreads();

    float x[4]; float ss2 = 0.f;
#pragma unroll
    for (int i = 0; i < 4; i++) {
        x[i] = v[i] * r1 * w1[t + 256 * i];
        ss2 += x[i] * x[i];
    }
    float w2s = warpSum(ss2);
    if (lane == 0) red[wid] = w2s;
    __syncthreads();
    if (wid == 0) {
        float q = (lane < 8) ? red[lane] : 0.f;
        q = warpSum(q);
        if (lane == 0) red[0] = rsqrtf(q / (float)D_ + EPS_);
    }
    __syncthreads();
    float r2 = red[0];
#pragma unroll
    for (int i = 0; i < 4; i++) {
        float val = x[i] * r2 * w2[t + 256 * i];
        size_t o = (size_t)token * D_ + t + 256 * i;
        __half h, l; split16(val, h, l);
        uhi[o] = h; ulo[o] = l;
    }
}

// =========================================================================
// 3-pass complex scan, no fp32 intermediate (CH_=128 chunks of CL_=16)
// =========================================================================
__global__ void scan_ends_kernel(const float* __restrict__ Are,
                                 const float* __restrict__ Aim,
                                 const float* __restrict__ ub,
                                 float* __restrict__ endr,
                                 float* __restrict__ endi) {
    int t = blockIdx.x * blockDim.x + threadIdx.x;
    int s = t % S_;
    int c = (t / S_) % CH_;
    int b = t / (S_ * CH_);
    float ar = Are[s], ai = Aim[s];
    float xr = 0.f, xi = 0.f;
    size_t base = (size_t)(b * L_ + c * CL_) * S2_ + s;
#pragma unroll
    for (int j = 0; j < CL_; j++) {
        size_t o = base + (size_t)j * S2_;
        float ur = ub[o], ui = ub[o + S_];
        float nr = fmaf(ar, xr, fmaf(-ai, xi, ur));
        float ni = fmaf(ar, xi, fmaf(ai, xr, ui));
        xr = nr; xi = ni;
    }
    endr[(b * CH_ + c) * S_ + s] = xr;
    endi[(b * CH_ + c) * S_ + s] = xi;
}

__global__ void scan_combine_kernel(const float* __restrict__ Are,
                                    const float* __restrict__ Aim,
                                    const float* __restrict__ endr,
                                    const float* __restrict__ endi,
                                    float* __restrict__ incr,
                                    float* __restrict__ inci) {
    int t = blockIdx.x * blockDim.x + threadIdx.x;
    if (t >= B_ * S_) return;
    int s = t % S_;
    int b = t / S_;
    float ar = Are[s], ai = Aim[s];
    float pr = 1.f, pi = 0.f;                    // A^CL_
#pragma unroll
    for (int j = 0; j < CL_; j++) {
        float nr = pr * ar - pi * ai;
        float ni = pr * ai + pi * ar;
        pr = nr; pi = ni;
    }
    float cr = 0.f, ci = 0.f;
    for (int c = 0; c < CH_; c++) {
        int idx = (b * CH_ + c) * S_ + s;
        incr[idx] = cr; inci[idx] = ci;
        float er = endr[idx], ei = endi[idx];
        float nr = fmaf(pr, cr, fmaf(-pi, ci, er));
        float ni = fmaf(pr, ci, fmaf(pi, cr, ei));
        cr = nr; ci = ni;
    }
}

__global__ void scan_final_kernel(const float* __restrict__ Are,
                                  const float* __restrict__ Aim,
                                  const float* __restrict__ incr,
                                  const float* __restrict__ inci,
                                  const float* __restrict__ ub,
                                  __half* __restrict__ xchi) {
    int t = blockIdx.x * blockDim.x + threadIdx.x;
    int s = t % S_;
    int c = (t / S_) % CH_;
    int b = t / (S_ * CH_);
    int cidx = (b * CH_ + c) * S_ + s;
    float xr = incr[cidx], xi = inci[cidx];      // state before chunk
    float ar = Are[s], ai = Aim[s];
    size_t base = (size_t)(b * L_ + c * CL_) * S2_ + s;
#pragma unroll
    for (int j = 0; j < CL_; j++) {
        size_t o = base + (size_t)j * S2_;
        float ur = ub[o], ui = ub[o + S_];
        float nr = fmaf(ar, xr, fmaf(-ai, xi, ur));
        float ni = fmaf(ar, xi, fmaf(ai, xr, ui));
        xr = nr; xi = ni;
        xchi[o]      = __float2half(xr);
        xchi[o + S_] = __float2half(xi);
    }
}

// =========================================================================
// converters
// =========================================================================
__global__ void ccat_kernel(const float* __restrict__ Cre,
                            const float* __restrict__ Cim,
                            __half* __restrict__ hi,
                            __half* __restrict__ lo) {
    int i = blockIdx.x * blockDim.x + threadIdx.x;
    int row = i >> 10;
    int d = i & 1023;
    float v = (row < S_) ? Cre[row * D_ + d] : -Cim[(row - S_) * D_ + d];
    __half h, l; split16(v, h, l);
    hi[i] = h; lo[i] = l;
}

__global__ void bcat_kernel(const float* __restrict__ Bre,
                            const float* __restrict__ Bim,
                            __half* __restrict__ hi,
                            __half* __restrict__ lo) {
    int i = blockIdx.x * blockDim.x + threadIdx.x;   // D_*S2_
    int d = i >> 9;
    int c = i & 511;
    float v = (c < S_) ? Bre[d * S_ + c] : Bim[d * S_ + (c - S_)];
    __half h, l; split16(v, h, l);
    hi[i] = h; lo[i] = l;
}

// fully parallel Hw -> fp16 conversion (4 floats per thread)
__global__ void wconvert_kernel(const float* __restrict__ Hw,
                                __half* __restrict__ whi) {
    size_t i = ((size_t)blockIdx.x * blockDim.x + threadIdx.x) * 4;
    float4 w = *(const float4*)(Hw + i);
    __half2 h01, h23;
    h01.x = __float2half(w.x); h01.y = __float2half(w.y);
    h23.x = __float2half(w.z); h23.y = __float2half(w.w);
    *(__half2*)(whi + i)     = h01;
    *(__half2*)(whi + i + 2) = h23;
}

// gb = Dp @ Hw + Hb, deterministic two-stage
__global__ void gbias_stage1_kernel(const float* __restrict__ Hw,
                                    const float* __restrict__ Dp,
                                    float* __restrict__ gpart) {
    int v = blockIdx.x * blockDim.x + threadIdx.x;   // V_ wide
    int d0 = blockIdx.y * (D_ / GB_SLICES);
    float acc = 0.f;
#pragma unroll 8
    for (int j = 0; j < D_ / GB_SLICES; j++)
        acc = fmaf(__ldg(Dp + d0 + j), Hw[(size_t)(d0 + j) * V_ + v], acc);
    gpart[(size_t)blockIdx.y * V_ + v] = acc;
}

__global__ void gbias_stage2_kernel(const float* __restrict__ gpart,
                                    const float* __restrict__ Hb,
                                    float* __restrict__ gb) {
    int v = blockIdx.x * blockDim.x + threadIdx.x;
    float acc = Hb[v];
#pragma unroll
    for (int k = 0; k < GB_SLICES; k++)
        acc += gpart[(size_t)k * V_ + v];
    gb[v] = acc;
}

// =========================================================================
// Split-fp16 HMMA GEMM. CTA 128x256, BK=32, 8 warps (2m x 4n), 3-stage.
// TERMS=3: AhiBhi + AloBhi + AhiBlo; TERMS=2: +AloBhi; TERMS=1: AhiBhi
// =========================================================================
#define GBM 128
#define GBN 256
#define GBK 32
#define A_STRIDE 80
#define B_STRIDE 528
#define A_SPLIT  10240
#define B_SPLIT  16896

template<int TERMS>
__global__ __launch_bounds__(256, 1)
void mma_gemm(const __half* __restrict__ Ahi,
              const __half* __restrict__ Alo,
              const __half* __restrict__ Bhi,
              const __half* __restrict__ Blo,
              float* __restrict__ Cf,
              __half* __restrict__ Chi,
              const float* __restrict__ bias,
              int Mdim, int Ndim, int Kdim) {
    constexpr int A_BYTES = (TERMS >= 2) ? 2 * A_SPLIT : A_SPLIT;
    constexpr int STAGE_BYTES = A_BYTES + ((TERMS == 3) ? 2 * B_SPLIT : B_SPLIT);
    extern __shared__ char smem[];
    uint32_t sbase = smem_to_u32(smem);
    const int tid = threadIdx.x;
    const int lane = tid & 31, wid = tid >> 5;
    const int wm = wid & 1, wn = wid >> 1;
    const int brow = blockIdx.x * GBM;
    const int bcol = blockIdx.y * GBN;
    const int lda = Kdim, ldb = Ndim;
    const int niter = Kdim / GBK;

    float acc[4][8][4];
#pragma unroll
    for (int i = 0; i < 4; i++)
#pragma unroll
        for (int j = 0; j < 8; j++)
#pragma unroll
            for (int k = 0; k < 4; k++) acc[i][j][k] = 0.f;

    auto load_stage = [&](int kt, int st) {
        const int k0 = kt * GBK;
        uint32_t sa = sbase + st * STAGE_BYTES;
#pragma unroll
        for (int i = 0; i < 2; i++) {
            int c = tid + i * 256;
            int r = c >> 2, ch = c & 3;
            uint32_t dst = sa + r * A_STRIDE + ch * 16;
            size_t src = (size_t)(brow + r) * lda + k0 + ch * 8;
            cp_async16(dst, Ahi + src);
            if (TERMS >= 2) cp_async16(dst + A_SPLIT, Alo + src);
        }
#pragma unroll
        for (int i = 0; i < 4; i++) {
            int c = tid + i * 256;
            int r = c >> 5, ch = c & 31;
            uint32_t dst = sa + A_BYTES + r * B_STRIDE + ch * 16;
            size_t src = (size_t)(k0 + r) * ldb + bcol + ch * 8;
            cp_async16(dst, Bhi + src);
            if (TERMS == 3) cp_async16(dst + B_SPLIT, Blo + src);
        }
    };

    load_stage(0, 0); CP_COMMIT();
    load_stage(1, 1); CP_COMMIT();

    for (int kt = 0; kt < niter; kt++) {
        if (kt + 2 < niter) {
            load_stage(kt + 2, (kt + 2) % 3);
            CP_COMMIT();
            CP_WAIT(2);
        } else if (kt + 2 == niter) {
            CP_WAIT(1);
        } else {
            CP_WAIT(0);
        }
        __syncthreads();

        uint32_t sa = sbase + (kt % 3) * STAGE_BYTES;
#pragma unroll
        for (int ks = 0; ks < 2; ks++) {
            uint32_t ah[4][4], al[4][4];
#pragma unroll
            for (int mf = 0; mf < 4; mf++) {
                uint32_t addr = sa + (wm * 64 + mf * 16 + (lane & 15)) * A_STRIDE
                              + ks * 32 + (lane >> 4) * 16;
                LDSM4(ah[mf][0], ah[mf][1], ah[mf][2], ah[mf][3], addr);
                if (TERMS >= 2)
                    LDSM4(al[mf][0], al[mf][1], al[mf][2], al[mf][3], addr + A_SPLIT);
            }
            uint32_t bh[8][2], bl[8][2];
#pragma unroll
            for (int g = 0; g < 4; g++) {
                uint32_t addr = sa + A_BYTES + (ks * 16 + (lane & 15)) * B_STRIDE
                              + (wn * 64 + g * 16 + (lane >> 4) * 8) * 2;
                uint32_t r0, r1, r2, r3;
                LDSM4T(r0, r1, r2, r3, addr);
                bh[2 * g][0] = r0; bh[2 * g][1] = r1;
                bh[2 * g + 1][0] = r2; bh[2 * g + 1][1] = r3;
                if (TERMS == 3) {
                    LDSM4T(r0, r1, r2, r3, addr + B_SPLIT);
                    bl[2 * g][0] = r0; bl[2 * g][1] = r1;
                    bl[2 * g + 1][0] = r2; bl[2 * g + 1][1] = r3;
                }
            }
#pragma unroll
            for (int mf = 0; mf < 4; mf++)
#pragma unroll
                for (int nf = 0; nf < 8; nf++) {
                    MMA_F16(acc[mf][nf], ah[mf][0], ah[mf][1], ah[mf][2], ah[mf][3],
                            bh[nf][0], bh[nf][1]);
                    if (TERMS >= 2)
                        MMA_F16(acc[mf][nf], al[mf][0], al[mf][1], al[mf][2], al[mf][3],
                                bh[nf][0], bh[nf][1]);
                    if (TERMS == 3)
                        MMA_F16(acc[mf][nf], ah[mf][0], ah[mf][1], ah[mf][2], ah[mf][3],
                                bl[nf][0], bl[nf][1]);
                }
        }
        __syncthreads();
    }

    if (Chi) {
#pragma unroll
        for (int mf = 0; mf < 4; mf++) {
            int r0 = brow + wm * 64 + mf * 16 + (lane >> 2);
#pragma unroll
            for (int nf = 0; nf < 8; nf++) {
                int c0 = bcol + wn * 64 + nf * 8 + (lane & 3) * 2;
#pragma unroll
                for (int half_ = 0; half_ < 2; half_++) {
                    __half2 hv;
                    hv.x = __float2half(acc[mf][nf][2 * half_]);
                    hv.y = __float2half(acc[mf][nf][2 * half_ + 1]);
                    *(__half2*)(Chi + (size_t)(r0 + 8 * half_) * Ndim + c0) = hv;
                }
            }
        }
    } else {
#pragma unroll
        for (int mf = 0; mf < 4; mf++) {
            int r0 = brow + wm * 64 + mf * 16 + (lane >> 2);
#pragma unroll
            for (int nf = 0; nf < 8; nf++) {
                int c0 = bcol + wn * 64 + nf * 8 + (lane & 3) * 2;
                float b0 = 0.f, b1 = 0.f;
                if (bias) { b0 = __ldg(bias + c0); b1 = __ldg(bias + c0 + 1); }
                float2 v0 = make_float2(acc[mf][nf][0] + b0, acc[mf][nf][1] + b1);
                float2 v1 = make_float2(acc[mf][nf][2] + b0, acc[mf][nf][3] + b1);
                *(float2*)(Cf + (size_t)r0 * Ndim + c0)       = v0;
                *(float2*)(Cf + (size_t)(r0 + 8) * Ndim + c0) = v1;
            }
        }
    }
}

// =========================================================================
extern "C" void kernel_launch(void* const* d_in, const int* in_sizes, int n_in,
                              void* d_out, int out_size) {
    const int*   ids = (const int*)  d_in[0];
    const float* emb = (const float*)d_in[1];
    const float* w1  = (const float*)d_in[2];
    const float* w2  = (const float*)d_in[3];
    const float* Are = (const float*)d_in[4];
    const float* Aim = (const float*)d_in[5];
    const float* Bre = (const float*)d_in[6];
    const float* Bim = (const float*)d_in[7];
    const float* Cre = (const float*)d_in[8];
    const float* Cim = (const float*)d_in[9];
    const float* Dp  = (const float*)d_in[10];
    const float* Hw  = (const float*)d_in[11];
    const float* Hb  = (const float*)d_in[12];
    float* out = (float*)d_out;

    float *ub, *endr, *endi, *incr, *inci, *gpart, *gb;
    __half *uhi, *ulo, *bchi, *bclo, *xchi, *cchi, *cclo, *whi, *Ghi;
    cudaGetSymbolAddress((void**)&ub,    g_ub);
    cudaGetSymbolAddress((void**)&endr,  g_endr);
    cudaGetSymbolAddress((void**)&endi,  g_endi);
    cudaGetSymbolAddress((void**)&incr,  g_incr);
    cudaGetSymbolAddress((void**)&inci,  g_inci);
    cudaGetSymbolAddress((void**)&gpart, g_gpart);
    cudaGetSymbolAddress((void**)&uhi,   g_uhi);
    cudaGetSymbolAddress((void**)&ulo,   g_ulo);
    cudaGetSymbolAddress((void**)&bchi,  g_bchi);
    cudaGetSymbolAddress((void**)&bclo,  g_bclo);
    cudaGetSymbolAddress((void**)&xchi,  g_xchi);
    cudaGetSymbolAddress((void**)&cchi,  g_cchi);
    cudaGetSymbolAddress((void**)&cclo,  g_cclo);
    cudaGetSymbolAddress((void**)&whi,   g_whi);
    cudaGetSymbolAddress((void**)&Ghi,   g_Ghi);
    cudaGetSymbolAddress((void**)&gb,    g_gb);

    const int SM3 = 3 * (2 * A_SPLIT + 2 * B_SPLIT);  // 162816
    const int SM2 = 3 * (2 * A_SPLIT + B_SPLIT);      // 112128
    const int SM1 = 3 * (A_SPLIT + B_SPLIT);          // 81408
    cudaFuncSetAttribute(mma_gemm<3>,
                         cudaFuncAttributeMaxDynamicSharedMemorySize, SM3);
    cudaFuncSetAttribute(mma_gemm<2>,
                         cudaFuncAttributeMaxDynamicSharedMemorySize, SM2);
    cudaFuncSetAttribute(mma_gemm<1>,
                         cudaFuncAttributeMaxDynamicSharedMemorySize, SM1);

    // ---- weight prep (fully parallel) ----
    wconvert_kernel<<<(int)(((size_t)D_ * V_ / 4) / 256), 256>>>(Hw, whi);
    gbias_stage1_kernel<<<dim3(V_ / 256, GB_SLICES), 256>>>(Hw, Dp, gpart);
    gbias_stage2_kernel<<<V_ / 256, 256>>>(gpart, Hb, gb);
    ccat_kernel<<<(S2_ * D_) / 256, 256>>>(Cre, Cim, cchi, cclo);
    bcat_kernel<<<(D_ * S2_) / 256, 256>>>(Bre, Bim, bchi, bclo);

    // G = Ccat @ Hw  [512, 32000]  (2-term; epilogue fp16)
    mma_gemm<2><<<dim3(S2_ / GBM, V_ / GBN), 256, SM2>>>(
        cchi, cclo, whi, nullptr, nullptr, Ghi, nullptr, S2_, V_, D_);

    // ---- activation chain ----
    embed_norm_kernel<<<M_, 256>>>(ids, emb, w1, w2, uhi, ulo);

    // uB = u @ Bcat  [4096, 512]  (3-term exact, fp32 out)
    mma_gemm<3><<<dim3(M_ / GBM, S2_ / GBN), 256, SM3>>>(
        uhi, ulo, bchi, bclo, ub, nullptr, nullptr, M_, S2_, D_);

    // 3-pass complex scan -> xchi (fp16), 256 CTAs per pass
    scan_ends_kernel<<<(B_ * CH_ * S_) / 256, 256>>>(Are, Aim, ub, endr, endi);
    scan_combine_kernel<<<(B_ * S_ + 255) / 256, 256>>>(Are, Aim, endr, endi, incr, inci);
    scan_final_kernel<<<(B_ * CH_ * S_) / 256, 256>>>(Are, Aim, incr, inci, ub, xchi);

    // logits = xchi @ Ghi + gb  [4096, 32000]  (1-term fp16)
    mma_gemm<1><<<dim3(M_ / GBM, V_ / GBN), 256, SM1>>>(
        xchi, nullptr, Ghi, nullptr, out, nullptr, gb, M_, V_, S2_);
}